// round 12
// baseline (speedup 1.0000x reference)
#include <cuda_runtime.h>
#include <cuda_fp16.h>
#include <math.h>
#include <stdint.h>

// Problem constants
#define B_  2
#define L_  1024
#define DM  1024
#define DI  2048
#define DS  16
#define DTR 64
#define KC  4
#define BL  (B_*L_)   // 2048

// ---------------- scratch (device globals) -----------------------------------
__device__ float g_xc [BL*DI];
__device__ float g_z  [BL*DI];
__device__ float g_xca[BL*DI];
__device__ float g_dBC[BL*96];
__device__ float g_del[BL*DI];

// fp16 operands for tensor-core GEMMs (A split hi/lo, B rounded once)
__device__ __half g_xh [BL*DM];
__device__ __half g_xl [BL*DM];
__device__ __half g_wih[2*DI*DM];
__device__ __half g_uh [BL*DI];
__device__ __half g_ul [BL*DI];
__device__ __half g_woh[DM*DI];

// ======================= PTX helpers (sm_80 baseline) =========================
__device__ __forceinline__ uint32_t smem_u32(const void* p){
    uint32_t a;
    asm("{ .reg .u64 t; cvta.to.shared.u64 t, %1; cvt.u32.u64 %0, t; }" : "=r"(a) : "l"(p));
    return a;
}
__device__ __forceinline__ void cp16(uint32_t dst, const void* src){
    asm volatile("cp.async.cg.shared.global [%0], [%1], 16;" :: "r"(dst), "l"(src));
}
__device__ __forceinline__ void cp_commit(){ asm volatile("cp.async.commit_group;" ::: "memory"); }
template<int N> __device__ __forceinline__ void cp_wait(){
    asm volatile("cp.async.wait_group %0;" :: "n"(N) : "memory");
}
__device__ __forceinline__ void ldsm_x4(uint32_t* r, uint32_t addr){
    asm volatile("ldmatrix.sync.aligned.m8n8.x4.shared.b16 {%0,%1,%2,%3}, [%4];"
        : "=r"(r[0]), "=r"(r[1]), "=r"(r[2]), "=r"(r[3]) : "r"(addr));
}
__device__ __forceinline__ void mma16816(float* c, const uint32_t* a, const uint32_t* b){
    asm volatile(
        "mma.sync.aligned.m16n8k16.row.col.f32.f16.f16.f32 "
        "{%0,%1,%2,%3}, {%4,%5,%6,%7}, {%8,%9}, {%0,%1,%2,%3};"
        : "+f"(c[0]), "+f"(c[1]), "+f"(c[2]), "+f"(c[3])
        : "r"(a[0]), "r"(a[1]), "r"(a[2]), "r"(a[3]), "r"(b[0]), "r"(b[1]));
}

// ===== HMMA GEMM v6: 128x128 CTA, 8 warps, warp 64x32, fp16x2 =================
// 4-stage cp.async pipeline, unpadded 64B rows + XOR-swizzle, 1 barrier/chunk.
// Klen = K iterated per CTA; lda = row stride; blockIdx.z selects K-slice.
// MODE 0: plain store. MODE 1: split g_xc/g_z at DI. MODE 2: atomicAdd (split-K).
#define ARR   (128*64)           // 8192 bytes per operand array (no padding)
#define STG   (3*ARR)            // 24576 bytes per stage (Ah, Al, Bh)
#define NSTG  4
#define MMA_SMEM (NSTG*STG + 1024)

template<int MODE>
__global__ __launch_bounds__(256, 2)
void mma_gemm(const __half* __restrict__ Ah, const __half* __restrict__ Al,
              const __half* __restrict__ Bh,
              int Klen, int lda, float* __restrict__ C, int ldc)
{
    extern __shared__ char sraw[];
    const uint32_t base = (smem_u32(sraw) + 1023) & ~1023u;   // bits 0-9 clear

    const int tid  = threadIdx.x;
    const int wid  = tid >> 5, lane = tid & 31;
    const int wm   = wid & 1;          // 2 warp-rows of 64
    const int wn   = wid >> 1;         // 4 warp-cols of 32
    const int bm   = blockIdx.y * 128, bn = blockIdx.x * 128;
    const size_t koff = (size_t)blockIdx.z * Klen;

    float acc[4][4][4];
#pragma unroll
    for (int i = 0; i < 4; i++)
#pragma unroll
        for (int j = 0; j < 4; j++)
#pragma unroll
            for (int q = 0; q < 4; q++) acc[i][j][q] = 0.f;

    // ---- stage loaders: 2 threads per row, 32B (= 2 swizzled 16B chunks) ----
    const int  row   = tid >> 1;
    const int  hs    = tid & 1;
    const int  rowsw = (row >> 1) & 3;                 // swizzle factor
    const uint32_t c0 = (uint32_t)(((2*hs)     ^ rowsw) << 4);
    const uint32_t c1 = (uint32_t)(((2*hs + 1) ^ rowsw) << 4);
    const char* sAh = (const char*)(Ah + (size_t)(bm + row) * lda + koff) + hs*32;
    const char* sAl = (const char*)(Al + (size_t)(bm + row) * lda + koff) + hs*32;
    const char* sBh = (const char*)(Bh + (size_t)(bn + row) * lda + koff) + hs*32;
    const uint32_t dst0 = base + row*64;

    #define LOAD_STAGE(c, st) do {                                          \
        uint32_t d = dst0 + (st)*STG;                                        \
        size_t   g = (size_t)(c)*64;                                         \
        cp16(d +         c0, sAh+g); cp16(d +         c1, sAh+g+16);         \
        cp16(d + ARR   + c0, sAl+g); cp16(d + ARR   + c1, sAl+g+16);         \
        cp16(d + 2*ARR + c0, sBh+g); cp16(d + 2*ARR + c1, sBh+g+16);         \
    } while(0)

    const int NCH = Klen >> 5;
    // prologue: chunks 0..2
    LOAD_STAGE(0, 0); cp_commit();
    if (NCH > 1) LOAD_STAGE(1, 1); cp_commit();
    if (NCH > 2) LOAD_STAGE(2, 2); cp_commit();

    // ldmatrix per-lane base addresses (swizzled chunk folded into base;
    // ks advance = XOR 32, valid because bits 4-5 of all other terms are 0)
    const int r15 = lane & 15;
    const int lch = lane >> 4;
    const int lsw = (r15 >> 1) & 3;
    const uint32_t apc = (uint32_t)((lch ^ lsw) << 4);
    const uint32_t aoff = base + (uint32_t)((wm*64 + r15)*64) + apc;
    const uint32_t boff = base + 2*ARR + (uint32_t)((wn*32 + r15)*64) + apc;

    int sc = 0;                          // compute-stage index = c % 4
    int sl = 3;                          // load-stage index   = (c+3) % 4
    for (int c = 0; c < NCH; c++){
        cp_wait<2>();
        __syncthreads();

        if (c + 3 < NCH) LOAD_STAGE(c + 3, sl);
        cp_commit();

        const uint32_t so = (uint32_t)sc * STG;
#pragma unroll
        for (int ks = 0; ks < 2; ks++){
            const uint32_t kx = (uint32_t)(ks << 5);
            uint32_t ah[4][4], al[4][4];
#pragma unroll
            for (int i = 0; i < 4; i++){
                ldsm_x4(ah[i], ((aoff + so +       (uint32_t)(i*1024))) ^ kx);
                ldsm_x4(al[i], ((aoff + so + ARR + (uint32_t)(i*1024))) ^ kx);
            }
            uint32_t bh[2][4];
#pragma unroll
            for (int jp = 0; jp < 2; jp++)
                ldsm_x4(bh[jp], ((boff + so + (uint32_t)(jp*1024))) ^ kx);
#pragma unroll
            for (int i = 0; i < 4; i++){
#pragma unroll
                for (int j = 0; j < 4; j++){
                    uint32_t bfh[2] = { bh[j>>1][j&1], bh[j>>1][2+(j&1)] };
                    mma16816(acc[i][j], ah[i], bfh);
                    mma16816(acc[i][j], al[i], bfh);
                }
            }
        }
        sc = (sc == 3) ? 0 : sc + 1;
        sl = (sl == 3) ? 0 : sl + 1;
    }
    #undef LOAD_STAGE

    // ---- epilogue ----
    float* Cb; int n0; int ld;
    if (MODE == 1){
        if (bn < DI){ Cb = g_xc; n0 = bn; } else { Cb = g_z; n0 = bn - DI; }
        ld = DI;
    } else { Cb = C; n0 = bn; ld = ldc; }

    const int g = lane >> 2, t = lane & 3;
#pragma unroll
    for (int i = 0; i < 4; i++){
        const int r0 = bm + wm*64 + i*16 + g;
#pragma unroll
        for (int j = 0; j < 4; j++){
            const int col = n0 + wn*32 + j*8 + t*2;
            if (MODE == 2){
                atomicAdd(Cb + (size_t)r0       * ld + col,     acc[i][j][0]);
                atomicAdd(Cb + (size_t)r0       * ld + col + 1, acc[i][j][1]);
                atomicAdd(Cb + (size_t)(r0 + 8) * ld + col,     acc[i][j][2]);
                atomicAdd(Cb + (size_t)(r0 + 8) * ld + col + 1, acc[i][j][3]);
            } else {
                float2 v0 = make_float2(acc[i][j][0], acc[i][j][1]);
                float2 v1 = make_float2(acc[i][j][2], acc[i][j][3]);
                *(float2*)(Cb + (size_t)r0       * ld + col) = v0;
                *(float2*)(Cb + (size_t)(r0 + 8) * ld + col) = v1;
            }
        }
    }
}

// ---------------- zero-fill (for split-K accumulation target) -----------------
__global__ __launch_bounds__(256)
void zero_out(float* __restrict__ p, int n4)
{
    int i = blockIdx.x * blockDim.x + threadIdx.x;
    if (i < n4) ((float4*)p)[i] = make_float4(0.f, 0.f, 0.f, 0.f);
}

// ---------------- fp32 -> (hi,lo) fp16 split ----------------------------------
__global__ __launch_bounds__(256)
void split_fp16(const float* __restrict__ in, __half* __restrict__ hi,
                __half* __restrict__ lo, int n4)
{
    int i = blockIdx.x * blockDim.x + threadIdx.x;
    if (i >= n4) return;
    float4 v = ((const float4*)in)[i];
    float a[4] = {v.x, v.y, v.z, v.w};
    __half h[4], l[4];
    #pragma unroll
    for (int k = 0; k < 4; k++){
        h[k] = __float2half_rn(a[k]);
        l[k] = __float2half_rn(a[k] - __half2float(h[k]));
    }
    ((__half2*)hi)[2*i]   = __halves2half2(h[0], h[1]);
    ((__half2*)hi)[2*i+1] = __halves2half2(h[2], h[3]);
    ((__half2*)lo)[2*i]   = __halves2half2(l[0], l[1]);
    ((__half2*)lo)[2*i+1] = __halves2half2(l[2], l[3]);
}

// ---------------- fp32 -> fp16 round (weights) --------------------------------
__global__ __launch_bounds__(256)
void cvt_fp16(const float* __restrict__ in, __half* __restrict__ out, int n4)
{
    int i = blockIdx.x * blockDim.x + threadIdx.x;
    if (i >= n4) return;
    float4 v = ((const float4*)in)[i];
    ((__half2*)out)[2*i]   = __halves2half2(__float2half_rn(v.x), __float2half_rn(v.y));
    ((__half2*)out)[2*i+1] = __halves2half2(__float2half_rn(v.z), __float2half_rn(v.w));
}

// ---------------- fp32 SIMT GEMM (delta GEMM, K=64) ---------------------------
__global__ __launch_bounds__(256)
void gemm_delta(const float* __restrict__ A, int lda,
                const float* __restrict__ W, int Kdim,
                float* __restrict__ C, int ldc,
                const float* __restrict__ bias)
{
    const int bm = blockIdx.y * 128;
    const int bn = blockIdx.x * 128;

    __shared__ float As[8][128];
    __shared__ float Bs[8][128];

    float acc[8][8];
#pragma unroll
    for (int i = 0; i < 8; i++)
#pragma unroll
        for (int j = 0; j < 8; j++) acc[i][j] = 0.f;

    const int tid  = threadIdx.x;
    const int arow = tid >> 1;
    const int acol = (tid & 1) * 4;
    const int trow = (tid >> 4) * 8;
    const int tcol = (tid & 15) * 8;

    const float* Aptr = A + (size_t)(bm + arow) * lda + acol;
    const float* Wptr = W + (size_t)(bn + arow) * Kdim + acol;

    for (int kt = 0; kt < Kdim; kt += 8) {
        float4 av = *(const float4*)(Aptr + kt);
        float4 wv = *(const float4*)(Wptr + kt);
        As[acol+0][arow] = av.x; As[acol+1][arow] = av.y;
        As[acol+2][arow] = av.z; As[acol+3][arow] = av.w;
        Bs[acol+0][arow] = wv.x; Bs[acol+1][arow] = wv.y;
        Bs[acol+2][arow] = wv.z; Bs[acol+3][arow] = wv.w;
        __syncthreads();

#pragma unroll
        for (int kk = 0; kk < 8; kk++) {
            float4 a0 = *(const float4*)&As[kk][trow];
            float4 a1 = *(const float4*)&As[kk][trow+4];
            float4 b0 = *(const float4*)&Bs[kk][tcol];
            float4 b1 = *(const float4*)&Bs[kk][tcol+4];
            float ar[8] = {a0.x,a0.y,a0.z,a0.w,a1.x,a1.y,a1.z,a1.w};
            float br[8] = {b0.x,b0.y,b0.z,b0.w,b1.x,b1.y,b1.z,b1.w};
#pragma unroll
            for (int i = 0; i < 8; i++)
#pragma unroll
                for (int j = 0; j < 8; j++)
                    acc[i][j] = fmaf(ar[i], br[j], acc[i][j]);
        }
        __syncthreads();
    }

#pragma unroll
    for (int i = 0; i < 8; i++) {
        const int m = bm + trow + i;
#pragma unroll
        for (int j = 0; j < 8; j++) {
            const int n = bn + tcol + j;
            float v = acc[i][j] + bias[n];
            float sp = (v > 20.f) ? v : log1pf(__expf(v));
            C[(size_t)m * ldc + n] = sp;
        }
    }
}

// ---------------- small tiled GEMM for dBC (N=96) ----------------------------
__global__ __launch_bounds__(256)
void gemm_small(const float* __restrict__ A, int lda,
                const float* __restrict__ W, int Kdim,
                float* __restrict__ C, int ldc)
{
    const int bm = blockIdx.y * 32;
    const int bn = blockIdx.x * 32;

    __shared__ float As[32][33];
    __shared__ float Ws[32][33];

    float acc[2][2] = {{0.f,0.f},{0.f,0.f}};

    const int tid  = threadIdx.x;
    const int lrow = tid >> 3;
    const int lcol = (tid & 7) * 4;
    const int tm   = (tid >> 4) * 2;
    const int tn   = (tid & 15) * 2;

    for (int kt = 0; kt < Kdim; kt += 32) {
        float4 av = *(const float4*)(A + (size_t)(bm + lrow) * lda + kt + lcol);
        float4 wv = *(const float4*)(W + (size_t)(bn + lrow) * Kdim + kt + lcol);
        As[lcol+0][lrow] = av.x; As[lcol+1][lrow] = av.y;
        As[lcol+2][lrow] = av.z; As[lcol+3][lrow] = av.w;
        Ws[lcol+0][lrow] = wv.x; Ws[lcol+1][lrow] = wv.y;
        Ws[lcol+2][lrow] = wv.z; Ws[lcol+3][lrow] = wv.w;
        __syncthreads();

#pragma unroll
        for (int kk = 0; kk < 32; kk++) {
            float a0 = As[kk][tm], a1 = As[kk][tm+1];
            float b0 = Ws[kk][tn], b1 = Ws[kk][tn+1];
            acc[0][0] = fmaf(a0, b0, acc[0][0]);
            acc[0][1] = fmaf(a0, b1, acc[0][1]);
            acc[1][0] = fmaf(a1, b0, acc[1][0]);
            acc[1][1] = fmaf(a1, b1, acc[1][1]);
        }
        __syncthreads();
    }

#pragma unroll
    for (int i = 0; i < 2; i++)
#pragma unroll
        for (int j = 0; j < 2; j++)
            C[(size_t)(bm + tm + i) * ldc + (bn + tn + j)] = acc[i][j];
}

// ---------------- depthwise causal conv (K=4) + bias + SiLU ------------------
__global__ __launch_bounds__(256)
void conv_silu_kernel(const float* __restrict__ cw, const float* __restrict__ cb)
{
    int idx = blockIdx.x * blockDim.x + threadIdx.x;
    if (idx >= BL * DI) return;
    int d  = idx % DI;
    int bl = idx / DI;
    int l  = bl % L_;
    int b  = bl / L_;

    float s = cb[d];
    const float* base = g_xc + (size_t)b * L_ * DI + d;
#pragma unroll
    for (int j = 0; j < KC; j++) {
        int ll = l + j - (KC - 1);
        if (ll >= 0) s = fmaf(base[(size_t)ll * DI], cw[d * KC + j], s);
    }
    g_xca[idx] = s / (1.f + __expf(-s));
}

// ---------------- selective scan + gate (R11 version) -------------------------
__global__ __launch_bounds__(64)
void scan_kernel(const float* __restrict__ A_log, const float* __restrict__ Dp)
{
    const int gtid = blockIdx.x * 64 + threadIdx.x;
    const int warp = gtid >> 5;
    const int lane = threadIdx.x & 31;
    const int half = lane >> 4;
    const int n    = lane & 15;
    const int c    = warp * 2 + half;
    const int b    = c / DI;
    const int d    = c % DI;

    const float Aval = -__expf(A_log[d * DS + n]);
    const float dp   = Dp[d];

    const size_t rbase = (size_t)b * L_ * DI + d;
    const float* pD = g_del + rbase;
    const float* pX = g_xca + rbase;
    const float* pZ = g_z   + rbase;
    const float* pB = g_dBC + (size_t)b * L_ * 96 + DTR + n;
    const float* pC = g_dBC + (size_t)b * L_ * 96 + DTR + DS + n;
    __half* pUh = g_uh + rbase;
    __half* pUl = g_ul + rbase;

    float h = 0.f;
    float dlt = pD[0], xv = pX[0], zv = pZ[0], Bn = pB[0], Cn = pC[0];

    for (int l = 0; l < L_; l++) {
        const int ln = (l + 1 < L_) ? (l + 1) : l;
        float dlt_n = pD[(size_t)ln * DI];
        float xv_n  = pX[(size_t)ln * DI];
        float zv_n  = pZ[(size_t)ln * DI];
        float Bn_n  = pB[(size_t)ln * 96];
        float Cn_n  = pC[(size_t)ln * 96];

        float a = __expf(dlt * Aval);
        h = fmaf(a, h, dlt * Bn * xv);
        float p = h * Cn;
        p += __shfl_xor_sync(0xffffffffu, p, 8);
        p += __shfl_xor_sync(0xffffffffu, p, 4);
        p += __shfl_xor_sync(0xffffffffu, p, 2);
        p += __shfl_xor_sync(0xffffffffu, p, 1);
        if (n == 0) {
            float y  = fmaf(dp, xv, p);
            float sz = zv / (1.f + __expf(-zv));
            float u  = y * sz;
            __half uh = __float2half_rn(u);
            __half ul = __float2half_rn(u - __half2float(uh));
            pUh[(size_t)l * DI] = uh;
            pUl[(size_t)l * DI] = ul;
        }
        dlt = dlt_n; xv = xv_n; zv = zv_n; Bn = Bn_n; Cn = Cn_n;
    }
}

// ---------------- launch ------------------------------------------------------
extern "C" void kernel_launch(void* const* d_in, const int* in_sizes, int n_in,
                              void* d_out, int out_size)
{
    const float* x      = (const float*)d_in[0];
    const float* W_in   = (const float*)d_in[1];
    const float* conv_w = (const float*)d_in[2];
    const float* conv_b = (const float*)d_in[3];
    const float* W_x    = (const float*)d_in[4];
    const float* W_dt   = (const float*)d_in[5];
    const float* b_dt   = (const float*)d_in[6];
    const float* A_log  = (const float*)d_in[7];
    const float* Dp     = (const float*)d_in[8];
    const float* W_out  = (const float*)d_in[9];
    float* out = (float*)d_out;

    float* p_xca; cudaGetSymbolAddress((void**)&p_xca, g_xca);
    float* p_dBC; cudaGetSymbolAddress((void**)&p_dBC, g_dBC);
    float* p_del; cudaGetSymbolAddress((void**)&p_del, g_del);

    __half *p_xh, *p_xl, *p_wih, *p_uh, *p_ul, *p_woh;
    cudaGetSymbolAddress((void**)&p_xh,  g_xh);
    cudaGetSymbolAddress((void**)&p_xl,  g_xl);
    cudaGetSymbolAddress((void**)&p_wih, g_wih);
    cudaGetSymbolAddress((void**)&p_uh,  g_uh);
    cudaGetSymbolAddress((void**)&p_ul,  g_ul);
    cudaGetSymbolAddress((void**)&p_woh, g_woh);

    cudaFuncSetAttribute(mma_gemm<0>, cudaFuncAttributeMaxDynamicSharedMemorySize, MMA_SMEM);
    cudaFuncSetAttribute(mma_gemm<1>, cudaFuncAttributeMaxDynamicSharedMemorySize, MMA_SMEM);
    cudaFuncSetAttribute(mma_gemm<2>, cudaFuncAttributeMaxDynamicSharedMemorySize, MMA_SMEM);

    // launches 1-3: conversions (keeps GEMM1 in the profiled 4th launch slot)
    {
        int n4 = (BL * DM) / 4;
        split_fp16<<<(n4 + 255) / 256, 256>>>(x, p_xh, p_xl, n4);          // 1
        n4 = (2 * DI * DM) / 4;
        cvt_fp16<<<(n4 + 255) / 256, 256>>>(W_in, p_wih, n4);              // 2
        n4 = (DM * DI) / 4;
        cvt_fp16<<<(n4 + 255) / 256, 256>>>(W_out, p_woh, n4);             // 3
    }
    // 4) xz = x @ W_in^T  (HMMA fp16x2, 4-stage swizzled) -> g_xc / g_z
    {
        dim3 grid(2 * DI / 128, BL / 128);   // (32, 16)
        mma_gemm<1><<<grid, 256, MMA_SMEM>>>(p_xh, p_xl, p_wih, DM, DM, nullptr, 0);
    }
    // 5) depthwise causal conv + bias + silu -> g_xca
    {
        int total = BL * DI;
        conv_silu_kernel<<<(total + 255) / 256, 256>>>(conv_w, conv_b);
    }
    // 6) dBC = xca @ W_x^T   [BL,96]
    {
        dim3 grid(96 / 32, BL / 32);
        gemm_small<<<grid, 256>>>(p_xca, DI, W_x, DI, p_dBC, 96);
    }
    // 7) delta = softplus(dBC[:, :64] @ W_dt^T + b_dt)  [BL, DI]
    {
        dim3 grid(DI / 128, BL / 128);
        gemm_delta<<<grid, 256>>>(p_dBC, 96, W_dt, DTR, p_del, DI, b_dt);
    }
    // 8) selective scan + D skip + gate -> g_uh/g_ul (64-thread blocks)
    {
        scan_kernel<<<B_ * DI / 4, 64>>>(A_log, Dp);
    }
    // 8b) zero output for split-K accumulation
    {
        int n4 = (BL * DM) / 4;
        zero_out<<<(n4 + 255) / 256, 256>>>(out, n4);
    }
    // 9) out = u @ W_out^T  (HMMA fp16x2, split-K=2, atomic accumulate)
    {
        dim3 grid(DM / 128, BL / 128, 2);    // (8, 16, 2) = 256 CTAs
        mma_gemm<2><<<grid, 256, MMA_SMEM>>>(p_uh, p_ul, p_woh, DI / 2, DI, out, DM);
    }
}

// round 13
// speedup vs baseline: 1.2029x; 1.2029x over previous
#include <cuda_runtime.h>
#include <cuda_fp16.h>
#include <math.h>
#include <stdint.h>

// Problem constants
#define B_  2
#define L_  1024
#define DM  1024
#define DI  2048
#define DS  16
#define DTR 64
#define KC  4
#define BL  (B_*L_)   // 2048

// scan chunking
#define SC_NCH 16           // chunks along L
#define SC_CL  (L_/SC_NCH)  // 64

// ---------------- scratch (device globals) -----------------------------------
__device__ float g_xc [BL*DI];
__device__ float g_z  [BL*DI];
__device__ float g_xca[BL*DI];
__device__ float g_dBC[BL*96];
__device__ float g_del[BL*DI];

// chunked-scan intermediates: [channel][chunk][state]
__device__ float g_hend [B_*DI*SC_NCH*DS];   // 4MB
__device__ float g_aprod[B_*DI*SC_NCH*DS];   // 4MB
__device__ float g_h0   [B_*DI*SC_NCH*DS];   // 4MB

// fp16 operands for tensor-core GEMMs (A split hi/lo, B rounded once)
__device__ __half g_xh [BL*DM];
__device__ __half g_xl [BL*DM];
__device__ __half g_wih[2*DI*DM];
__device__ __half g_uh [BL*DI];
__device__ __half g_ul [BL*DI];
__device__ __half g_woh[DM*DI];

// ======================= PTX helpers (sm_80 baseline) =========================
__device__ __forceinline__ uint32_t smem_u32(const void* p){
    uint32_t a;
    asm("{ .reg .u64 t; cvta.to.shared.u64 t, %1; cvt.u32.u64 %0, t; }" : "=r"(a) : "l"(p));
    return a;
}
__device__ __forceinline__ void cp16(uint32_t dst, const void* src){
    asm volatile("cp.async.cg.shared.global [%0], [%1], 16;" :: "r"(dst), "l"(src));
}
__device__ __forceinline__ void cp_commit(){ asm volatile("cp.async.commit_group;" ::: "memory"); }
template<int N> __device__ __forceinline__ void cp_wait(){
    asm volatile("cp.async.wait_group %0;" :: "n"(N) : "memory");
}
__device__ __forceinline__ void ldsm_x4(uint32_t* r, uint32_t addr){
    asm volatile("ldmatrix.sync.aligned.m8n8.x4.shared.b16 {%0,%1,%2,%3}, [%4];"
        : "=r"(r[0]), "=r"(r[1]), "=r"(r[2]), "=r"(r[3]) : "r"(addr));
}
__device__ __forceinline__ void mma16816(float* c, const uint32_t* a, const uint32_t* b){
    asm volatile(
        "mma.sync.aligned.m16n8k16.row.col.f32.f16.f16.f32 "
        "{%0,%1,%2,%3}, {%4,%5,%6,%7}, {%8,%9}, {%0,%1,%2,%3};"
        : "+f"(c[0]), "+f"(c[1]), "+f"(c[2]), "+f"(c[3])
        : "r"(a[0]), "r"(a[1]), "r"(a[2]), "r"(a[3]), "r"(b[0]), "r"(b[1]));
}

// ===== HMMA GEMM: 128x128 CTA, 8 warps, warp 64x32, fp16x2, 4-stage swizzled ==
#define ARR   (128*64)
#define STG   (3*ARR)
#define NSTG  4
#define MMA_SMEM (NSTG*STG + 1024)

template<int MODE>
__global__ __launch_bounds__(256, 2)
void mma_gemm(const __half* __restrict__ Ah, const __half* __restrict__ Al,
              const __half* __restrict__ Bh,
              int Klen, int lda, float* __restrict__ C, int ldc)
{
    extern __shared__ char sraw[];
    const uint32_t base = (smem_u32(sraw) + 1023) & ~1023u;

    const int tid  = threadIdx.x;
    const int wid  = tid >> 5, lane = tid & 31;
    const int wm   = wid & 1;
    const int wn   = wid >> 1;
    const int bm   = blockIdx.y * 128, bn = blockIdx.x * 128;

    float acc[4][4][4];
#pragma unroll
    for (int i = 0; i < 4; i++)
#pragma unroll
        for (int j = 0; j < 4; j++)
#pragma unroll
            for (int q = 0; q < 4; q++) acc[i][j][q] = 0.f;

    const int  row   = tid >> 1;
    const int  hs    = tid & 1;
    const int  rowsw = (row >> 1) & 3;
    const uint32_t c0 = (uint32_t)(((2*hs)     ^ rowsw) << 4);
    const uint32_t c1 = (uint32_t)(((2*hs + 1) ^ rowsw) << 4);
    const char* sAh = (const char*)(Ah + (size_t)(bm + row) * lda) + hs*32;
    const char* sAl = (const char*)(Al + (size_t)(bm + row) * lda) + hs*32;
    const char* sBh = (const char*)(Bh + (size_t)(bn + row) * lda) + hs*32;
    const uint32_t dst0 = base + row*64;

    #define LOAD_STAGE(c, st) do {                                          \
        uint32_t d = dst0 + (st)*STG;                                        \
        size_t   g = (size_t)(c)*64;                                         \
        cp16(d +         c0, sAh+g); cp16(d +         c1, sAh+g+16);         \
        cp16(d + ARR   + c0, sAl+g); cp16(d + ARR   + c1, sAl+g+16);         \
        cp16(d + 2*ARR + c0, sBh+g); cp16(d + 2*ARR + c1, sBh+g+16);         \
    } while(0)

    const int NCH = Klen >> 5;
    LOAD_STAGE(0, 0); cp_commit();
    if (NCH > 1) LOAD_STAGE(1, 1); cp_commit();
    if (NCH > 2) LOAD_STAGE(2, 2); cp_commit();

    const int r15 = lane & 15;
    const int lch = lane >> 4;
    const int lsw = (r15 >> 1) & 3;
    const uint32_t apc = (uint32_t)((lch ^ lsw) << 4);
    const uint32_t aoff = base + (uint32_t)((wm*64 + r15)*64) + apc;
    const uint32_t boff = base + 2*ARR + (uint32_t)((wn*32 + r15)*64) + apc;

    int sc = 0, sl = 3;
    for (int c = 0; c < NCH; c++){
        cp_wait<2>();
        __syncthreads();

        if (c + 3 < NCH) LOAD_STAGE(c + 3, sl);
        cp_commit();

        const uint32_t so = (uint32_t)sc * STG;
#pragma unroll
        for (int ks = 0; ks < 2; ks++){
            const uint32_t kx = (uint32_t)(ks << 5);
            uint32_t ah[4][4], al[4][4];
#pragma unroll
            for (int i = 0; i < 4; i++){
                ldsm_x4(ah[i], ((aoff + so +       (uint32_t)(i*1024))) ^ kx);
                ldsm_x4(al[i], ((aoff + so + ARR + (uint32_t)(i*1024))) ^ kx);
            }
            uint32_t bh[2][4];
#pragma unroll
            for (int jp = 0; jp < 2; jp++)
                ldsm_x4(bh[jp], ((boff + so + (uint32_t)(jp*1024))) ^ kx);
#pragma unroll
            for (int i = 0; i < 4; i++){
#pragma unroll
                for (int j = 0; j < 4; j++){
                    uint32_t bfh[2] = { bh[j>>1][j&1], bh[j>>1][2+(j&1)] };
                    mma16816(acc[i][j], ah[i], bfh);
                    mma16816(acc[i][j], al[i], bfh);
                }
            }
        }
        sc = (sc == 3) ? 0 : sc + 1;
        sl = (sl == 3) ? 0 : sl + 1;
    }
    #undef LOAD_STAGE

    float* Cb; int n0; int ld;
    if (MODE == 1){
        if (bn < DI){ Cb = g_xc; n0 = bn; } else { Cb = g_z; n0 = bn - DI; }
        ld = DI;
    } else { Cb = C; n0 = bn; ld = ldc; }

    const int g = lane >> 2, t = lane & 3;
#pragma unroll
    for (int i = 0; i < 4; i++){
        const int r0 = bm + wm*64 + i*16 + g;
#pragma unroll
        for (int j = 0; j < 4; j++){
            const int col = n0 + wn*32 + j*8 + t*2;
            float2 v0 = make_float2(acc[i][j][0], acc[i][j][1]);
            float2 v1 = make_float2(acc[i][j][2], acc[i][j][3]);
            *(float2*)(Cb + (size_t)r0       * ld + col) = v0;
            *(float2*)(Cb + (size_t)(r0 + 8) * ld + col) = v1;
        }
    }
}

// ---------------- fp32 -> (hi,lo) fp16 split ----------------------------------
__global__ __launch_bounds__(256)
void split_fp16(const float* __restrict__ in, __half* __restrict__ hi,
                __half* __restrict__ lo, int n4)
{
    int i = blockIdx.x * blockDim.x + threadIdx.x;
    if (i >= n4) return;
    float4 v = ((const float4*)in)[i];
    float a[4] = {v.x, v.y, v.z, v.w};
    __half h[4], l[4];
    #pragma unroll
    for (int k = 0; k < 4; k++){
        h[k] = __float2half_rn(a[k]);
        l[k] = __float2half_rn(a[k] - __half2float(h[k]));
    }
    ((__half2*)hi)[2*i]   = __halves2half2(h[0], h[1]);
    ((__half2*)hi)[2*i+1] = __halves2half2(h[2], h[3]);
    ((__half2*)lo)[2*i]   = __halves2half2(l[0], l[1]);
    ((__half2*)lo)[2*i+1] = __halves2half2(l[2], l[3]);
}

// ---------------- fp32 -> fp16 round (weights) --------------------------------
__global__ __launch_bounds__(256)
void cvt_fp16(const float* __restrict__ in, __half* __restrict__ out, int n4)
{
    int i = blockIdx.x * blockDim.x + threadIdx.x;
    if (i >= n4) return;
    float4 v = ((const float4*)in)[i];
    ((__half2*)out)[2*i]   = __halves2half2(__float2half_rn(v.x), __float2half_rn(v.y));
    ((__half2*)out)[2*i+1] = __halves2half2(__float2half_rn(v.z), __float2half_rn(v.w));
}

// ---------------- fp32 SIMT GEMM (delta GEMM, K=64) ---------------------------
__global__ __launch_bounds__(256)
void gemm_delta(const float* __restrict__ A, int lda,
                const float* __restrict__ W, int Kdim,
                float* __restrict__ C, int ldc,
                const float* __restrict__ bias)
{
    const int bm = blockIdx.y * 128;
    const int bn = blockIdx.x * 128;

    __shared__ float As[8][128];
    __shared__ float Bs[8][128];

    float acc[8][8];
#pragma unroll
    for (int i = 0; i < 8; i++)
#pragma unroll
        for (int j = 0; j < 8; j++) acc[i][j] = 0.f;

    const int tid  = threadIdx.x;
    const int arow = tid >> 1;
    const int acol = (tid & 1) * 4;
    const int trow = (tid >> 4) * 8;
    const int tcol = (tid & 15) * 8;

    const float* Aptr = A + (size_t)(bm + arow) * lda + acol;
    const float* Wptr = W + (size_t)(bn + arow) * Kdim + acol;

    for (int kt = 0; kt < Kdim; kt += 8) {
        float4 av = *(const float4*)(Aptr + kt);
        float4 wv = *(const float4*)(Wptr + kt);
        As[acol+0][arow] = av.x; As[acol+1][arow] = av.y;
        As[acol+2][arow] = av.z; As[acol+3][arow] = av.w;
        Bs[acol+0][arow] = wv.x; Bs[acol+1][arow] = wv.y;
        Bs[acol+2][arow] = wv.z; Bs[acol+3][arow] = wv.w;
        __syncthreads();

#pragma unroll
        for (int kk = 0; kk < 8; kk++) {
            float4 a0 = *(const float4*)&As[kk][trow];
            float4 a1 = *(const float4*)&As[kk][trow+4];
            float4 b0 = *(const float4*)&Bs[kk][tcol];
            float4 b1 = *(const float4*)&Bs[kk][tcol+4];
            float ar[8] = {a0.x,a0.y,a0.z,a0.w,a1.x,a1.y,a1.z,a1.w};
            float br[8] = {b0.x,b0.y,b0.z,b0.w,b1.x,b1.y,b1.z,b1.w};
#pragma unroll
            for (int i = 0; i < 8; i++)
#pragma unroll
                for (int j = 0; j < 8; j++)
                    acc[i][j] = fmaf(ar[i], br[j], acc[i][j]);
        }
        __syncthreads();
    }

#pragma unroll
    for (int i = 0; i < 8; i++) {
        const int m = bm + trow + i;
#pragma unroll
        for (int j = 0; j < 8; j++) {
            const int n = bn + tcol + j;
            float v = acc[i][j] + bias[n];
            float sp = (v > 20.f) ? v : log1pf(__expf(v));
            C[(size_t)m * ldc + n] = sp;
        }
    }
}

// ---------------- small tiled GEMM for dBC (N=96) ----------------------------
__global__ __launch_bounds__(256)
void gemm_small(const float* __restrict__ A, int lda,
                const float* __restrict__ W, int Kdim,
                float* __restrict__ C, int ldc)
{
    const int bm = blockIdx.y * 32;
    const int bn = blockIdx.x * 32;

    __shared__ float As[32][33];
    __shared__ float Ws[32][33];

    float acc[2][2] = {{0.f,0.f},{0.f,0.f}};

    const int tid  = threadIdx.x;
    const int lrow = tid >> 3;
    const int lcol = (tid & 7) * 4;
    const int tm   = (tid >> 4) * 2;
    const int tn   = (tid & 15) * 2;

    for (int kt = 0; kt < Kdim; kt += 32) {
        float4 av = *(const float4*)(A + (size_t)(bm + lrow) * lda + kt + lcol);
        float4 wv = *(const float4*)(W + (size_t)(bn + lrow) * Kdim + kt + lcol);
        As[lcol+0][lrow] = av.x; As[lcol+1][lrow] = av.y;
        As[lcol+2][lrow] = av.z; As[lcol+3][lrow] = av.w;
        Ws[lcol+0][lrow] = wv.x; Ws[lcol+1][lrow] = wv.y;
        Ws[lcol+2][lrow] = wv.z; Ws[lcol+3][lrow] = wv.w;
        __syncthreads();

#pragma unroll
        for (int kk = 0; kk < 32; kk++) {
            float a0 = As[kk][tm], a1 = As[kk][tm+1];
            float b0 = Ws[kk][tn], b1 = Ws[kk][tn+1];
            acc[0][0] = fmaf(a0, b0, acc[0][0]);
            acc[0][1] = fmaf(a0, b1, acc[0][1]);
            acc[1][0] = fmaf(a1, b0, acc[1][0]);
            acc[1][1] = fmaf(a1, b1, acc[1][1]);
        }
        __syncthreads();
    }

#pragma unroll
    for (int i = 0; i < 2; i++)
#pragma unroll
        for (int j = 0; j < 2; j++)
            C[(size_t)(bm + tm + i) * ldc + (bn + tn + j)] = acc[i][j];
}

// ---------------- depthwise causal conv (K=4) + bias + SiLU ------------------
__global__ __launch_bounds__(256)
void conv_silu_kernel(const float* __restrict__ cw, const float* __restrict__ cb)
{
    int idx = blockIdx.x * blockDim.x + threadIdx.x;
    if (idx >= BL * DI) return;
    int d  = idx % DI;
    int bl = idx / DI;
    int l  = bl % L_;
    int b  = bl / L_;

    float s = cb[d];
    const float* base = g_xc + (size_t)b * L_ * DI + d;
#pragma unroll
    for (int j = 0; j < KC; j++) {
        int ll = l + j - (KC - 1);
        if (ll >= 0) s = fmaf(base[(size_t)ll * DI], cw[d * KC + j], s);
    }
    g_xca[idx] = s / (1.f + __expf(-s));
}

// ============== chunked scan: phase A (local scan per chunk) ==================
// warp -> (channel pair, chunk); lane: half=channel, n=state.
__global__ __launch_bounds__(64)
void scanA(const float* __restrict__ A_log)
{
    const int gwarp = blockIdx.x * 2 + (threadIdx.x >> 5);
    const int chunk = gwarp & (SC_NCH - 1);
    const int wpair = gwarp >> 4;
    const int lane  = threadIdx.x & 31;
    const int half  = lane >> 4;
    const int n     = lane & 15;
    const int c     = wpair * 2 + half;
    const int b     = c / DI;
    const int d     = c % DI;

    const float Aval = -__expf(A_log[d * DS + n]);

    const size_t rbase = (size_t)b * L_ * DI + d;
    const float* pD = g_del + rbase;
    const float* pX = g_xca + rbase;
    const float* pB = g_dBC + (size_t)b * L_ * 96 + DTR + n;

    float h = 0.f, P = 1.f;
    const int l0 = chunk * SC_CL;
    for (int q = 0; q < SC_CL; q++){
        const size_t l = (size_t)(l0 + q);
        float dlt = pD[l * DI];
        float xv  = pX[l * DI];
        float Bn  = pB[l * 96];
        float a = __expf(dlt * Aval);
        h = fmaf(a, h, dlt * Bn * xv);
        P *= a;
    }
    const size_t o = ((size_t)c * SC_NCH + chunk) * DS + n;
    g_hend [o] = h;
    g_aprod[o] = P;
}

// ============== chunked scan: phase B (scan over chunk states) ================
__global__ __launch_bounds__(256)
void scanB(void)
{
    const int idx = blockIdx.x * 256 + threadIdx.x;   // over B_*DI*DS
    if (idx >= B_ * DI * DS) return;
    const int c = idx >> 4;
    const int n = idx & 15;

    float h0 = 0.f;
#pragma unroll
    for (int j = 0; j < SC_NCH; j++){
        const size_t o = ((size_t)c * SC_NCH + j) * DS + n;
        g_h0[o] = h0;
        h0 = fmaf(g_aprod[o], h0, g_hend[o]);
    }
}

// ============== chunked scan: phase C (emit u with seeded h) ==================
__global__ __launch_bounds__(64)
void scanC(const float* __restrict__ A_log, const float* __restrict__ Dp)
{
    const int gwarp = blockIdx.x * 2 + (threadIdx.x >> 5);
    const int chunk = gwarp & (SC_NCH - 1);
    const int wpair = gwarp >> 4;
    const int lane  = threadIdx.x & 31;
    const int half  = lane >> 4;
    const int n     = lane & 15;
    const int c     = wpair * 2 + half;
    const int b     = c / DI;
    const int d     = c % DI;

    const float Aval = -__expf(A_log[d * DS + n]);
    const float dp   = Dp[d];

    const size_t rbase = (size_t)b * L_ * DI + d;
    const float* pD = g_del + rbase;
    const float* pX = g_xca + rbase;
    const float* pZ = g_z   + rbase;
    const float* pB = g_dBC + (size_t)b * L_ * 96 + DTR + n;
    const float* pC = g_dBC + (size_t)b * L_ * 96 + DTR + DS + n;
    __half* pUh = g_uh + rbase;
    __half* pUl = g_ul + rbase;

    float h = g_h0[((size_t)c * SC_NCH + chunk) * DS + n];

    const int l0 = chunk * SC_CL;
    for (int q = 0; q < SC_CL; q++){
        const size_t l = (size_t)(l0 + q);
        float dlt = pD[l * DI];
        float xv  = pX[l * DI];
        float zv  = pZ[l * DI];
        float Bn  = pB[l * 96];
        float Cn  = pC[l * 96];

        float a = __expf(dlt * Aval);
        h = fmaf(a, h, dlt * Bn * xv);
        float p = h * Cn;
        p += __shfl_xor_sync(0xffffffffu, p, 8);
        p += __shfl_xor_sync(0xffffffffu, p, 4);
        p += __shfl_xor_sync(0xffffffffu, p, 2);
        p += __shfl_xor_sync(0xffffffffu, p, 1);
        if (n == 0){
            float y  = fmaf(dp, xv, p);
            float sz = zv / (1.f + __expf(-zv));
            float u  = y * sz;
            __half uh = __float2half_rn(u);
            __half ul = __float2half_rn(u - __half2float(uh));
            pUh[l * DI] = uh;
            pUl[l * DI] = ul;
        }
    }
}

// ---------------- launch ------------------------------------------------------
extern "C" void kernel_launch(void* const* d_in, const int* in_sizes, int n_in,
                              void* d_out, int out_size)
{
    const float* x      = (const float*)d_in[0];
    const float* W_in   = (const float*)d_in[1];
    const float* conv_w = (const float*)d_in[2];
    const float* conv_b = (const float*)d_in[3];
    const float* W_x    = (const float*)d_in[4];
    const float* W_dt   = (const float*)d_in[5];
    const float* b_dt   = (const float*)d_in[6];
    const float* A_log  = (const float*)d_in[7];
    const float* Dp     = (const float*)d_in[8];
    const float* W_out  = (const float*)d_in[9];
    float* out = (float*)d_out;

    float* p_xca; cudaGetSymbolAddress((void**)&p_xca, g_xca);
    float* p_dBC; cudaGetSymbolAddress((void**)&p_dBC, g_dBC);
    float* p_del; cudaGetSymbolAddress((void**)&p_del, g_del);

    __half *p_xh, *p_xl, *p_wih, *p_uh, *p_ul, *p_woh;
    cudaGetSymbolAddress((void**)&p_xh,  g_xh);
    cudaGetSymbolAddress((void**)&p_xl,  g_xl);
    cudaGetSymbolAddress((void**)&p_wih, g_wih);
    cudaGetSymbolAddress((void**)&p_uh,  g_uh);
    cudaGetSymbolAddress((void**)&p_ul,  g_ul);
    cudaGetSymbolAddress((void**)&p_woh, g_woh);

    cudaFuncSetAttribute(mma_gemm<0>, cudaFuncAttributeMaxDynamicSharedMemorySize, MMA_SMEM);
    cudaFuncSetAttribute(mma_gemm<1>, cudaFuncAttributeMaxDynamicSharedMemorySize, MMA_SMEM);

    // launches 1-3: conversions (keeps GEMM1 in the profiled 4th launch slot)
    {
        int n4 = (BL * DM) / 4;
        split_fp16<<<(n4 + 255) / 256, 256>>>(x, p_xh, p_xl, n4);
        n4 = (2 * DI * DM) / 4;
        cvt_fp16<<<(n4 + 255) / 256, 256>>>(W_in, p_wih, n4);
        n4 = (DM * DI) / 4;
        cvt_fp16<<<(n4 + 255) / 256, 256>>>(W_out, p_woh, n4);
    }
    // 4) xz = x @ W_in^T  (HMMA fp16x2) -> g_xc / g_z
    {
        dim3 grid(2 * DI / 128, BL / 128);
        mma_gemm<1><<<grid, 256, MMA_SMEM>>>(p_xh, p_xl, p_wih, DM, DM, nullptr, 0);
    }
    // 5) depthwise causal conv + bias + silu -> g_xca
    {
        int total = BL * DI;
        conv_silu_kernel<<<(total + 255) / 256, 256>>>(conv_w, conv_b);
    }
    // 6) dBC = xca @ W_x^T   [BL,96]
    {
        dim3 grid(96 / 32, BL / 32);
        gemm_small<<<grid, 256>>>(p_xca, DI, W_x, DI, p_dBC, 96);
    }
    // 7) delta = softplus(dBC[:, :64] @ W_dt^T + b_dt)  [BL, DI]
    {
        dim3 grid(DI / 128, BL / 128);
        gemm_delta<<<grid, 256>>>(p_dBC, 96, W_dt, DTR, p_del, DI, b_dt);
    }
    // 8) chunked selective scan: A (local), B (chunk-state scan), C (emit)
    {
        // warps = (B*DI/2 channel-pairs) * 16 chunks; 2 warps per 64-thr block
        int nwarps = (B_ * DI / 2) * SC_NCH;
        scanA<<<nwarps / 2, 64>>>(A_log);
        scanB<<<(B_ * DI * DS + 255) / 256, 256>>>();
        scanC<<<nwarps / 2, 64>>>(A_log, Dp);
    }
    // 9) out = u @ W_out^T  (HMMA fp16x2)
    {
        dim3 grid(DM / 128, BL / 128);
        mma_gemm<0><<<grid, 256, MMA_SMEM>>>(p_uh, p_ul, p_woh, DI, DI, out, DM);
    }
}

// round 14
// speedup vs baseline: 1.2682x; 1.0543x over previous
#include <cuda_runtime.h>
#include <cuda_fp16.h>
#include <math.h>
#include <stdint.h>

// Problem constants
#define B_  2
#define L_  1024
#define DM  1024
#define DI  2048
#define DS  16
#define DTR 64
#define KC  4
#define BL  (B_*L_)   // 2048

// scan chunking
#define SC_NCH 16
#define SC_CL  (L_/SC_NCH)  // 64

// ---------------- scratch (device globals) -----------------------------------
__device__ float g_xc [BL*DI];
__device__ float g_z  [BL*DI];
__device__ float g_xca[BL*DI];
__device__ float g_dBC[BL*96];
__device__ float g_del[BL*DI];

__device__ float g_hend [B_*DI*SC_NCH*DS];
__device__ float g_aprod[B_*DI*SC_NCH*DS];
__device__ float g_h0   [B_*DI*SC_NCH*DS];

__device__ __half g_xh [BL*DM];
__device__ __half g_xl [BL*DM];
__device__ __half g_wih[2*DI*DM];
__device__ __half g_uh [BL*DI];
__device__ __half g_ul [BL*DI];
__device__ __half g_woh[DM*DI];

// ======================= PTX helpers (sm_80 baseline) =========================
__device__ __forceinline__ uint32_t smem_u32(const void* p){
    uint32_t a;
    asm("{ .reg .u64 t; cvta.to.shared.u64 t, %1; cvt.u32.u64 %0, t; }" : "=r"(a) : "l"(p));
    return a;
}
__device__ __forceinline__ void cp16(uint32_t dst, const void* src){
    asm volatile("cp.async.cg.shared.global [%0], [%1], 16;" :: "r"(dst), "l"(src));
}
__device__ __forceinline__ void cp_commit(){ asm volatile("cp.async.commit_group;" ::: "memory"); }
template<int N> __device__ __forceinline__ void cp_wait(){
    asm volatile("cp.async.wait_group %0;" :: "n"(N) : "memory");
}
__device__ __forceinline__ void ldsm_x4(uint32_t* r, uint32_t addr){
    asm volatile("ldmatrix.sync.aligned.m8n8.x4.shared.b16 {%0,%1,%2,%3}, [%4];"
        : "=r"(r[0]), "=r"(r[1]), "=r"(r[2]), "=r"(r[3]) : "r"(addr));
}
__device__ __forceinline__ void mma16816(float* c, const uint32_t* a, const uint32_t* b){
    asm volatile(
        "mma.sync.aligned.m16n8k16.row.col.f32.f16.f16.f32 "
        "{%0,%1,%2,%3}, {%4,%5,%6,%7}, {%8,%9}, {%0,%1,%2,%3};"
        : "+f"(c[0]), "+f"(c[1]), "+f"(c[2]), "+f"(c[3])
        : "r"(a[0]), "r"(a[1]), "r"(a[2]), "r"(a[3]), "r"(b[0]), "r"(b[1]));
}

// ===== HMMA GEMM: 128x128 CTA, 8 warps, warp 64x32, fp16x2, 4-stage swizzled ==
#define ARR   (128*64)
#define STG   (3*ARR)
#define NSTG  4
#define MMA_SMEM (NSTG*STG + 1024)

template<int MODE>
__global__ __launch_bounds__(256, 2)
void mma_gemm(const __half* __restrict__ Ah, const __half* __restrict__ Al,
              const __half* __restrict__ Bh,
              int Klen, int lda, float* __restrict__ C, int ldc)
{
    extern __shared__ char sraw[];
    const uint32_t base = (smem_u32(sraw) + 1023) & ~1023u;

    const int tid  = threadIdx.x;
    const int wid  = tid >> 5, lane = tid & 31;
    const int wm   = wid & 1;
    const int wn   = wid >> 1;
    const int bm   = blockIdx.y * 128, bn = blockIdx.x * 128;

    float acc[4][4][4];
#pragma unroll
    for (int i = 0; i < 4; i++)
#pragma unroll
        for (int j = 0; j < 4; j++)
#pragma unroll
            for (int q = 0; q < 4; q++) acc[i][j][q] = 0.f;

    const int  row   = tid >> 1;
    const int  hs    = tid & 1;
    const int  rowsw = (row >> 1) & 3;
    const uint32_t c0 = (uint32_t)(((2*hs)     ^ rowsw) << 4);
    const uint32_t c1 = (uint32_t)(((2*hs + 1) ^ rowsw) << 4);
    const char* sAh = (const char*)(Ah + (size_t)(bm + row) * lda) + hs*32;
    const char* sAl = (const char*)(Al + (size_t)(bm + row) * lda) + hs*32;
    const char* sBh = (const char*)(Bh + (size_t)(bn + row) * lda) + hs*32;
    const uint32_t dst0 = base + row*64;

    #define LOAD_STAGE(c, st) do {                                          \
        uint32_t d = dst0 + (st)*STG;                                        \
        size_t   g = (size_t)(c)*64;                                         \
        cp16(d +         c0, sAh+g); cp16(d +         c1, sAh+g+16);         \
        cp16(d + ARR   + c0, sAl+g); cp16(d + ARR   + c1, sAl+g+16);         \
        cp16(d + 2*ARR + c0, sBh+g); cp16(d + 2*ARR + c1, sBh+g+16);         \
    } while(0)

    const int NCH = Klen >> 5;
    LOAD_STAGE(0, 0); cp_commit();
    if (NCH > 1) LOAD_STAGE(1, 1); cp_commit();
    if (NCH > 2) LOAD_STAGE(2, 2); cp_commit();

    const int r15 = lane & 15;
    const int lch = lane >> 4;
    const int lsw = (r15 >> 1) & 3;
    const uint32_t apc = (uint32_t)((lch ^ lsw) << 4);
    const uint32_t aoff = base + (uint32_t)((wm*64 + r15)*64) + apc;
    const uint32_t boff = base + 2*ARR + (uint32_t)((wn*32 + r15)*64) + apc;

    int sc = 0, sl = 3;
    for (int c = 0; c < NCH; c++){
        cp_wait<2>();
        __syncthreads();

        if (c + 3 < NCH) LOAD_STAGE(c + 3, sl);
        cp_commit();

        const uint32_t so = (uint32_t)sc * STG;
#pragma unroll
        for (int ks = 0; ks < 2; ks++){
            const uint32_t kx = (uint32_t)(ks << 5);
            uint32_t ah[4][4], al[4][4];
#pragma unroll
            for (int i = 0; i < 4; i++){
                ldsm_x4(ah[i], ((aoff + so +       (uint32_t)(i*1024))) ^ kx);
                ldsm_x4(al[i], ((aoff + so + ARR + (uint32_t)(i*1024))) ^ kx);
            }
            uint32_t bh[2][4];
#pragma unroll
            for (int jp = 0; jp < 2; jp++)
                ldsm_x4(bh[jp], ((boff + so + (uint32_t)(jp*1024))) ^ kx);
#pragma unroll
            for (int i = 0; i < 4; i++){
#pragma unroll
                for (int j = 0; j < 4; j++){
                    uint32_t bfh[2] = { bh[j>>1][j&1], bh[j>>1][2+(j&1)] };
                    mma16816(acc[i][j], ah[i], bfh);
                    mma16816(acc[i][j], al[i], bfh);
                }
            }
        }
        sc = (sc == 3) ? 0 : sc + 1;
        sl = (sl == 3) ? 0 : sl + 1;
    }
    #undef LOAD_STAGE

    float* Cb; int n0; int ld;
    if (MODE == 1){
        if (bn < DI){ Cb = g_xc; n0 = bn; } else { Cb = g_z; n0 = bn - DI; }
        ld = DI;
    } else { Cb = C; n0 = bn; ld = ldc; }

    const int g = lane >> 2, t = lane & 3;
#pragma unroll
    for (int i = 0; i < 4; i++){
        const int r0 = bm + wm*64 + i*16 + g;
#pragma unroll
        for (int j = 0; j < 4; j++){
            const int col = n0 + wn*32 + j*8 + t*2;
            float2 v0 = make_float2(acc[i][j][0], acc[i][j][1]);
            float2 v1 = make_float2(acc[i][j][2], acc[i][j][3]);
            *(float2*)(Cb + (size_t)r0       * ld + col) = v0;
            *(float2*)(Cb + (size_t)(r0 + 8) * ld + col) = v1;
        }
    }
}

// ---------------- zero-fill ----------------------------------------------------
__global__ __launch_bounds__(256)
void zero_out(float* __restrict__ p, int n4)
{
    int i = blockIdx.x * blockDim.x + threadIdx.x;
    if (i < n4) ((float4*)p)[i] = make_float4(0.f, 0.f, 0.f, 0.f);
}

// ---------------- fp32 -> (hi,lo) fp16 split, x4 batched ----------------------
__global__ __launch_bounds__(256)
void split_fp16(const float* __restrict__ in, __half* __restrict__ hi,
                __half* __restrict__ lo, int n4)
{
    int i0 = blockIdx.x * blockDim.x * 4 + threadIdx.x;
    float4 v[4];
    #pragma unroll
    for (int k = 0; k < 4; k++){
        int i = i0 + k * blockDim.x;
        if (i < n4) v[k] = ((const float4*)in)[i];
    }
    #pragma unroll
    for (int k = 0; k < 4; k++){
        int i = i0 + k * blockDim.x;
        if (i >= n4) continue;
        float a[4] = {v[k].x, v[k].y, v[k].z, v[k].w};
        __half h[4], l[4];
        #pragma unroll
        for (int q = 0; q < 4; q++){
            h[q] = __float2half_rn(a[q]);
            l[q] = __float2half_rn(a[q] - __half2float(h[q]));
        }
        ((__half2*)hi)[2*i]   = __halves2half2(h[0], h[1]);
        ((__half2*)hi)[2*i+1] = __halves2half2(h[2], h[3]);
        ((__half2*)lo)[2*i]   = __halves2half2(l[0], l[1]);
        ((__half2*)lo)[2*i+1] = __halves2half2(l[2], l[3]);
    }
}

// ---------------- fp32 -> fp16 round, x4 batched --------------------------------
__global__ __launch_bounds__(256)
void cvt_fp16(const float* __restrict__ in, __half* __restrict__ out, int n4)
{
    int i0 = blockIdx.x * blockDim.x * 4 + threadIdx.x;
    float4 v[4];
    #pragma unroll
    for (int k = 0; k < 4; k++){
        int i = i0 + k * blockDim.x;
        if (i < n4) v[k] = ((const float4*)in)[i];
    }
    #pragma unroll
    for (int k = 0; k < 4; k++){
        int i = i0 + k * blockDim.x;
        if (i >= n4) continue;
        ((__half2*)out)[2*i]   = __halves2half2(__float2half_rn(v[k].x), __float2half_rn(v[k].y));
        ((__half2*)out)[2*i+1] = __halves2half2(__float2half_rn(v[k].z), __float2half_rn(v[k].w));
    }
}

// ---------------- fp32 SIMT GEMM (delta GEMM, K=64) ---------------------------
__global__ __launch_bounds__(256)
void gemm_delta(const float* __restrict__ A, int lda,
                const float* __restrict__ W, int Kdim,
                float* __restrict__ C, int ldc,
                const float* __restrict__ bias)
{
    const int bm = blockIdx.y * 128;
    const int bn = blockIdx.x * 128;

    __shared__ float As[8][128];
    __shared__ float Bs[8][128];

    float acc[8][8];
#pragma unroll
    for (int i = 0; i < 8; i++)
#pragma unroll
        for (int j = 0; j < 8; j++) acc[i][j] = 0.f;

    const int tid  = threadIdx.x;
    const int arow = tid >> 1;
    const int acol = (tid & 1) * 4;
    const int trow = (tid >> 4) * 8;
    const int tcol = (tid & 15) * 8;

    const float* Aptr = A + (size_t)(bm + arow) * lda + acol;
    const float* Wptr = W + (size_t)(bn + arow) * Kdim + acol;

    for (int kt = 0; kt < Kdim; kt += 8) {
        float4 av = *(const float4*)(Aptr + kt);
        float4 wv = *(const float4*)(Wptr + kt);
        As[acol+0][arow] = av.x; As[acol+1][arow] = av.y;
        As[acol+2][arow] = av.z; As[acol+3][arow] = av.w;
        Bs[acol+0][arow] = wv.x; Bs[acol+1][arow] = wv.y;
        Bs[acol+2][arow] = wv.z; Bs[acol+3][arow] = wv.w;
        __syncthreads();

#pragma unroll
        for (int kk = 0; kk < 8; kk++) {
            float4 a0 = *(const float4*)&As[kk][trow];
            float4 a1 = *(const float4*)&As[kk][trow+4];
            float4 b0 = *(const float4*)&Bs[kk][tcol];
            float4 b1 = *(const float4*)&Bs[kk][tcol+4];
            float ar[8] = {a0.x,a0.y,a0.z,a0.w,a1.x,a1.y,a1.z,a1.w};
            float br[8] = {b0.x,b0.y,b0.z,b0.w,b1.x,b1.y,b1.z,b1.w};
#pragma unroll
            for (int i = 0; i < 8; i++)
#pragma unroll
                for (int j = 0; j < 8; j++)
                    acc[i][j] = fmaf(ar[i], br[j], acc[i][j]);
        }
        __syncthreads();
    }

#pragma unroll
    for (int i = 0; i < 8; i++) {
        const int m = bm + trow + i;
#pragma unroll
        for (int j = 0; j < 8; j++) {
            const int n = bn + tcol + j;
            float v = acc[i][j] + bias[n];
            float sp = (v > 20.f) ? v : log1pf(__expf(v));
            C[(size_t)m * ldc + n] = sp;
        }
    }
}

// ------- small GEMM v2: 32x96 tile, split-K=4, atomic accumulate --------------
// grid (SKS, BL/32); reads xca once (no N-tile re-read).
#define SKS 4
__global__ __launch_bounds__(256)
void gemm_small2(const float* __restrict__ A, int lda,
                 const float* __restrict__ W, int Kdim,
                 float* __restrict__ C, int ldc)
{
    const int bm = blockIdx.y * 32;
    const int k0 = blockIdx.x * (Kdim / SKS);
    const int k1 = k0 + Kdim / SKS;

    __shared__ float As[32][33];
    __shared__ float Ws[32][97];

    float acc[2][6];
#pragma unroll
    for (int i = 0; i < 2; i++)
#pragma unroll
        for (int j = 0; j < 6; j++) acc[i][j] = 0.f;

    const int tid  = threadIdx.x;
    const int lrow = tid >> 3;
    const int lcol = (tid & 7) * 4;
    const int tm   = (tid >> 4) * 2;
    const int tn   = (tid & 15) * 6;

    for (int kt = k0; kt < k1; kt += 32) {
        float4 av = *(const float4*)(A + (size_t)(bm + lrow) * lda + kt + lcol);
        As[lcol+0][lrow] = av.x; As[lcol+1][lrow] = av.y;
        As[lcol+2][lrow] = av.z; As[lcol+3][lrow] = av.w;
        #pragma unroll
        for (int q = 0; q < 3; q++){
            int idx  = tid + q * 256;        // 0..767
            int wrow = idx >> 3;             // 0..95
            int wc4  = (idx & 7) * 4;
            float4 wv = *(const float4*)(W + (size_t)wrow * Kdim + kt + wc4);
            Ws[wc4+0][wrow] = wv.x; Ws[wc4+1][wrow] = wv.y;
            Ws[wc4+2][wrow] = wv.z; Ws[wc4+3][wrow] = wv.w;
        }
        __syncthreads();

#pragma unroll
        for (int kk = 0; kk < 32; kk++) {
            float a0 = As[kk][tm], a1 = As[kk][tm+1];
            float b[6];
            #pragma unroll
            for (int j = 0; j < 6; j++) b[j] = Ws[kk][tn+j];
            #pragma unroll
            for (int j = 0; j < 6; j++){
                acc[0][j] = fmaf(a0, b[j], acc[0][j]);
                acc[1][j] = fmaf(a1, b[j], acc[1][j]);
            }
        }
        __syncthreads();
    }

#pragma unroll
    for (int i = 0; i < 2; i++)
#pragma unroll
        for (int j = 0; j < 6; j++)
            atomicAdd(C + (size_t)(bm + tm + i) * ldc + (tn + j), acc[i][j]);
}

// ------- depthwise causal conv + bias + SiLU: 4 outputs/thread, float4 --------
__global__ __launch_bounds__(256)
void conv_silu_kernel(const float* __restrict__ cw, const float* __restrict__ cb)
{
    int i = blockIdx.x * blockDim.x + threadIdx.x;      // over BL*DI/4
    if (i >= BL * DI / 4) return;
    const int d4 = (i % (DI/4)) * 4;
    const int bl = i / (DI/4);
    const int l  = bl % L_;
    const int b  = bl / L_;

    float4 s = *(const float4*)(cb + d4);
    // taps for channels d4..d4+3: cw rows are 4 floats each, consecutive
    float4 W0 = *(const float4*)(cw + (d4+0)*4);
    float4 W1 = *(const float4*)(cw + (d4+1)*4);
    float4 W2 = *(const float4*)(cw + (d4+2)*4);
    float4 W3 = *(const float4*)(cw + (d4+3)*4);

    const float* base = g_xc + (size_t)b * L_ * DI + d4;
    float4 v[KC];
#pragma unroll
    for (int j = 0; j < KC; j++){
        int ll = l + j - (KC - 1);
        v[j] = (ll >= 0) ? *(const float4*)(base + (size_t)ll * DI)
                         : make_float4(0.f, 0.f, 0.f, 0.f);
    }
    // j-th tap weights: component j of each W row
    s.x = fmaf(v[0].x, W0.x, s.x); s.x = fmaf(v[1].x, W0.y, s.x);
    s.x = fmaf(v[2].x, W0.z, s.x); s.x = fmaf(v[3].x, W0.w, s.x);
    s.y = fmaf(v[0].y, W1.x, s.y); s.y = fmaf(v[1].y, W1.y, s.y);
    s.y = fmaf(v[2].y, W1.z, s.y); s.y = fmaf(v[3].y, W1.w, s.y);
    s.z = fmaf(v[0].z, W2.x, s.z); s.z = fmaf(v[1].z, W2.y, s.z);
    s.z = fmaf(v[2].z, W2.z, s.z); s.z = fmaf(v[3].z, W2.w, s.z);
    s.w = fmaf(v[0].w, W3.x, s.w); s.w = fmaf(v[1].w, W3.y, s.w);
    s.w = fmaf(v[2].w, W3.z, s.w); s.w = fmaf(v[3].w, W3.w, s.w);

    float4 o;
    o.x = s.x / (1.f + __expf(-s.x));
    o.y = s.y / (1.f + __expf(-s.y));
    o.z = s.z / (1.f + __expf(-s.z));
    o.w = s.w / (1.f + __expf(-s.w));
    *(float4*)(g_xca + (size_t)bl * DI + d4) = o;
}

// ============== chunked scan: phase A ========================================
__global__ __launch_bounds__(64)
void scanA(const float* __restrict__ A_log)
{
    const int gwarp = blockIdx.x * 2 + (threadIdx.x >> 5);
    const int chunk = gwarp & (SC_NCH - 1);
    const int wpair = gwarp >> 4;
    const int lane  = threadIdx.x & 31;
    const int half  = lane >> 4;
    const int n     = lane & 15;
    const int c     = wpair * 2 + half;
    const int b     = c / DI;
    const int d     = c % DI;

    const float Aval = -__expf(A_log[d * DS + n]);

    const size_t rbase = (size_t)b * L_ * DI + d;
    const float* pD = g_del + rbase;
    const float* pX = g_xca + rbase;
    const float* pB = g_dBC + (size_t)b * L_ * 96 + DTR + n;

    float h = 0.f, P = 1.f;
    const int l0 = chunk * SC_CL;
    for (int q = 0; q < SC_CL; q++){
        const size_t l = (size_t)(l0 + q);
        float dlt = pD[l * DI];
        float xv  = pX[l * DI];
        float Bn  = pB[l * 96];
        float a = __expf(dlt * Aval);
        h = fmaf(a, h, dlt * Bn * xv);
        P *= a;
    }
    const size_t o = ((size_t)c * SC_NCH + chunk) * DS + n;
    g_hend [o] = h;
    g_aprod[o] = P;
}

// ============== chunked scan: phase B ========================================
__global__ __launch_bounds__(256)
void scanB(void)
{
    const int idx = blockIdx.x * 256 + threadIdx.x;
    if (idx >= B_ * DI * DS) return;
    const int c = idx >> 4;
    const int n = idx & 15;

    float h0 = 0.f;
#pragma unroll
    for (int j = 0; j < SC_NCH; j++){
        const size_t o = ((size_t)c * SC_NCH + j) * DS + n;
        g_h0[o] = h0;
        h0 = fmaf(g_aprod[o], h0, g_hend[o]);
    }
}

// ============== chunked scan: phase C ========================================
__global__ __launch_bounds__(64)
void scanC(const float* __restrict__ A_log, const float* __restrict__ Dp)
{
    const int gwarp = blockIdx.x * 2 + (threadIdx.x >> 5);
    const int chunk = gwarp & (SC_NCH - 1);
    const int wpair = gwarp >> 4;
    const int lane  = threadIdx.x & 31;
    const int half  = lane >> 4;
    const int n     = lane & 15;
    const int c     = wpair * 2 + half;
    const int b     = c / DI;
    const int d     = c % DI;

    const float Aval = -__expf(A_log[d * DS + n]);
    const float dp   = Dp[d];

    const size_t rbase = (size_t)b * L_ * DI + d;
    const float* pD = g_del + rbase;
    const float* pX = g_xca + rbase;
    const float* pZ = g_z   + rbase;
    const float* pB = g_dBC + (size_t)b * L_ * 96 + DTR + n;
    const float* pC = g_dBC + (size_t)b * L_ * 96 + DTR + DS + n;
    __half* pUh = g_uh + rbase;
    __half* pUl = g_ul + rbase;

    float h = g_h0[((size_t)c * SC_NCH + chunk) * DS + n];

    const int l0 = chunk * SC_CL;
    for (int q = 0; q < SC_CL; q++){
        const size_t l = (size_t)(l0 + q);
        float dlt = pD[l * DI];
        float xv  = pX[l * DI];
        float zv  = pZ[l * DI];
        float Bn  = pB[l * 96];
        float Cn  = pC[l * 96];

        float a = __expf(dlt * Aval);
        h = fmaf(a, h, dlt * Bn * xv);
        float p = h * Cn;
        p += __shfl_xor_sync(0xffffffffu, p, 8);
        p += __shfl_xor_sync(0xffffffffu, p, 4);
        p += __shfl_xor_sync(0xffffffffu, p, 2);
        p += __shfl_xor_sync(0xffffffffu, p, 1);
        if (n == 0){
            float y  = fmaf(dp, xv, p);
            float sz = zv / (1.f + __expf(-zv));
            float u  = y * sz;
            __half uh = __float2half_rn(u);
            __half ul = __float2half_rn(u - __half2float(uh));
            pUh[l * DI] = uh;
            pUl[l * DI] = ul;
        }
    }
}

// ---------------- launch ------------------------------------------------------
extern "C" void kernel_launch(void* const* d_in, const int* in_sizes, int n_in,
                              void* d_out, int out_size)
{
    const float* x      = (const float*)d_in[0];
    const float* W_in   = (const float*)d_in[1];
    const float* conv_w = (const float*)d_in[2];
    const float* conv_b = (const float*)d_in[3];
    const float* W_x    = (const float*)d_in[4];
    const float* W_dt   = (const float*)d_in[5];
    const float* b_dt   = (const float*)d_in[6];
    const float* A_log  = (const float*)d_in[7];
    const float* Dp     = (const float*)d_in[8];
    const float* W_out  = (const float*)d_in[9];
    float* out = (float*)d_out;

    float* p_xca; cudaGetSymbolAddress((void**)&p_xca, g_xca);
    float* p_dBC; cudaGetSymbolAddress((void**)&p_dBC, g_dBC);
    float* p_del; cudaGetSymbolAddress((void**)&p_del, g_del);

    __half *p_xh, *p_xl, *p_wih, *p_uh, *p_ul, *p_woh;
    cudaGetSymbolAddress((void**)&p_xh,  g_xh);
    cudaGetSymbolAddress((void**)&p_xl,  g_xl);
    cudaGetSymbolAddress((void**)&p_wih, g_wih);
    cudaGetSymbolAddress((void**)&p_uh,  g_uh);
    cudaGetSymbolAddress((void**)&p_ul,  g_ul);
    cudaGetSymbolAddress((void**)&p_woh, g_woh);

    cudaFuncSetAttribute(mma_gemm<0>, cudaFuncAttributeMaxDynamicSharedMemorySize, MMA_SMEM);
    cudaFuncSetAttribute(mma_gemm<1>, cudaFuncAttributeMaxDynamicSharedMemorySize, MMA_SMEM);

    // launches 1-3: conversions (x4 batched; GEMM1 stays in profiled slot 4)
    {
        int n4 = (BL * DM) / 4;
        split_fp16<<<(n4 + 1023) / 1024, 256>>>(x, p_xh, p_xl, n4);
        n4 = (2 * DI * DM) / 4;
        cvt_fp16<<<(n4 + 1023) / 1024, 256>>>(W_in, p_wih, n4);
        n4 = (DM * DI) / 4;
        cvt_fp16<<<(n4 + 1023) / 1024, 256>>>(W_out, p_woh, n4);
    }
    // 4) xz = x @ W_in^T  (HMMA fp16x2) -> g_xc / g_z
    {
        dim3 grid(2 * DI / 128, BL / 128);
        mma_gemm<1><<<grid, 256, MMA_SMEM>>>(p_xh, p_xl, p_wih, DM, DM, nullptr, 0);
    }
    // 5) depthwise causal conv + bias + silu -> g_xca (4 outputs/thread)
    {
        int total = BL * DI / 4;
        conv_silu_kernel<<<(total + 255) / 256, 256>>>(conv_w, conv_b);
    }
    // 6) dBC = xca @ W_x^T  (32x96 tile, split-K=4, atomic)
    {
        zero_out<<<(BL * 96 / 4 + 255) / 256, 256>>>(p_dBC, BL * 96 / 4);
        dim3 grid(SKS, BL / 32);
        gemm_small2<<<grid, 256>>>(p_xca, DI, W_x, DI, p_dBC, 96);
    }
    // 7) delta = softplus(dBC[:, :64] @ W_dt^T + b_dt)
    {
        dim3 grid(DI / 128, BL / 128);
        gemm_delta<<<grid, 256>>>(p_dBC, 96, W_dt, DTR, p_del, DI, b_dt);
    }
    // 8) chunked selective scan
    {
        int nwarps = (B_ * DI / 2) * SC_NCH;
        scanA<<<nwarps / 2, 64>>>(A_log);
        scanB<<<(B_ * DI * DS + 255) / 256, 256>>>();
        scanC<<<nwarps / 2, 64>>>(A_log, Dp);
    }
    // 9) out = u @ W_out^T  (HMMA fp16x2)
    {
        dim3 grid(DM / 128, BL / 128);
        mma_gemm<0><<<grid, 256, MMA_SMEM>>>(p_uh, p_ul, p_woh, DI, DI, out, DM);
    }
}

// round 15
// speedup vs baseline: 1.3229x; 1.0432x over previous
#include <cuda_runtime.h>
#include <cuda_fp16.h>
#include <math.h>
#include <stdint.h>

// Problem constants
#define B_  2
#define L_  1024
#define DM  1024
#define DI  2048
#define DS  16
#define DTR 64
#define KC  4
#define BL  (B_*L_)   // 2048

// scan chunking
#define SC_NCH 16
#define SC_CL  (L_/SC_NCH)  // 64

// ---------------- scratch (device globals) -----------------------------------
__device__ float g_xc [BL*DI];
__device__ float g_z  [BL*DI];
__device__ float g_xca[BL*DI];
__device__ float g_dBC[BL*96];
__device__ float g_del[BL*DI];

__device__ float g_hend [B_*DI*SC_NCH*DS];
__device__ float g_aprod[B_*DI*SC_NCH*DS];
__device__ float g_h0   [B_*DI*SC_NCH*DS];

__device__ __half g_xh [BL*DM];
__device__ __half g_xl [BL*DM];
__device__ __half g_wih[2*DI*DM];
__device__ __half g_uh [BL*DI];
__device__ __half g_ul [BL*DI];
__device__ __half g_woh[DM*DI];
__device__ __half g_dch[BL*DTR];
__device__ __half g_dcl[BL*DTR];
__device__ __half g_wdh[DI*DTR];
__device__ __half g_wdl[DI*DTR];

// ======================= PTX helpers (sm_80 baseline) =========================
__device__ __forceinline__ uint32_t smem_u32(const void* p){
    uint32_t a;
    asm("{ .reg .u64 t; cvta.to.shared.u64 t, %1; cvt.u32.u64 %0, t; }" : "=r"(a) : "l"(p));
    return a;
}
__device__ __forceinline__ void cp16(uint32_t dst, const void* src){
    asm volatile("cp.async.cg.shared.global [%0], [%1], 16;" :: "r"(dst), "l"(src));
}
__device__ __forceinline__ void cp_commit(){ asm volatile("cp.async.commit_group;" ::: "memory"); }
template<int N> __device__ __forceinline__ void cp_wait(){
    asm volatile("cp.async.wait_group %0;" :: "n"(N) : "memory");
}
__device__ __forceinline__ void ldsm_x4(uint32_t* r, uint32_t addr){
    asm volatile("ldmatrix.sync.aligned.m8n8.x4.shared.b16 {%0,%1,%2,%3}, [%4];"
        : "=r"(r[0]), "=r"(r[1]), "=r"(r[2]), "=r"(r[3]) : "r"(addr));
}
__device__ __forceinline__ void mma16816(float* c, const uint32_t* a, const uint32_t* b){
    asm volatile(
        "mma.sync.aligned.m16n8k16.row.col.f32.f16.f16.f32 "
        "{%0,%1,%2,%3}, {%4,%5,%6,%7}, {%8,%9}, {%0,%1,%2,%3};"
        : "+f"(c[0]), "+f"(c[1]), "+f"(c[2]), "+f"(c[3])
        : "r"(a[0]), "r"(a[1]), "r"(a[2]), "r"(a[3]), "r"(b[0]), "r"(b[1]));
}

// ===== HMMA GEMM: 128x128 CTA, 8 warps, warp 64x32, XOR-swizzled cp.async =====
// MODE 0: fp16x2 plain store.  MODE 1: fp16x2, split g_xc/g_z at DI.
// MODE 3: fp16x3 (4 arrays, 2 stages), bias+softplus epilogue (delta GEMM).
#define ARR (128*64)

template<int MODE>
__global__ __launch_bounds__(256, 2)
void mma_gemm(const __half* __restrict__ Ah, const __half* __restrict__ Al,
              const __half* __restrict__ Bh, const __half* __restrict__ Bl,
              const float* __restrict__ bias,
              int Klen, int lda, float* __restrict__ C, int ldc)
{
    constexpr int NARR  = (MODE == 3) ? 4 : 3;
    constexpr int NSTG  = (MODE == 3) ? 2 : 4;
    constexpr int STG_  = NARR * ARR;
    constexpr int WAITN = NSTG - 2;

    extern __shared__ char sraw[];
    const uint32_t base = (smem_u32(sraw) + 1023) & ~1023u;

    const int tid  = threadIdx.x;
    const int wid  = tid >> 5, lane = tid & 31;
    const int wm   = wid & 1;
    const int wn   = wid >> 1;
    const int bm   = blockIdx.y * 128, bn = blockIdx.x * 128;

    float acc[4][4][4];
#pragma unroll
    for (int i = 0; i < 4; i++)
#pragma unroll
        for (int j = 0; j < 4; j++)
#pragma unroll
            for (int q = 0; q < 4; q++) acc[i][j][q] = 0.f;

    const int  row   = tid >> 1;
    const int  hs    = tid & 1;
    const int  rowsw = (row >> 1) & 3;
    const uint32_t c0 = (uint32_t)(((2*hs)     ^ rowsw) << 4);
    const uint32_t c1 = (uint32_t)(((2*hs + 1) ^ rowsw) << 4);
    const char* sAh = (const char*)(Ah + (size_t)(bm + row) * lda) + hs*32;
    const char* sAl = (const char*)(Al + (size_t)(bm + row) * lda) + hs*32;
    const char* sBh = (const char*)(Bh + (size_t)(bn + row) * lda) + hs*32;
    const char* sBl = (MODE == 3) ? (const char*)(Bl + (size_t)(bn + row) * lda) + hs*32 : nullptr;
    const uint32_t dst0 = base + row*64;

    #define LOAD_STAGE(c, st) do {                                          \
        uint32_t d = dst0 + (st)*STG_;                                       \
        size_t   g = (size_t)(c)*64;                                         \
        cp16(d +         c0, sAh+g); cp16(d +         c1, sAh+g+16);         \
        cp16(d + ARR   + c0, sAl+g); cp16(d + ARR   + c1, sAl+g+16);         \
        cp16(d + 2*ARR + c0, sBh+g); cp16(d + 2*ARR + c1, sBh+g+16);         \
        if (MODE == 3){                                                      \
            cp16(d + 3*ARR + c0, sBl+g); cp16(d + 3*ARR + c1, sBl+g+16);     \
        }                                                                    \
    } while(0)

    const int NCH = Klen >> 5;
    // prologue: chunks 0..NSTG-2
#pragma unroll
    for (int p = 0; p < NSTG - 1; p++){
        if (p < NCH) LOAD_STAGE(p, p);
        cp_commit();
    }

    const int r15 = lane & 15;
    const int lch = lane >> 4;
    const int lsw = (r15 >> 1) & 3;
    const uint32_t apc = (uint32_t)((lch ^ lsw) << 4);
    const uint32_t aoff = base + (uint32_t)((wm*64 + r15)*64) + apc;
    const uint32_t boff = base + 2*ARR + (uint32_t)((wn*32 + r15)*64) + apc;

    int sc = 0, sl = NSTG - 1;
    for (int c = 0; c < NCH; c++){
        cp_wait<WAITN>();
        __syncthreads();

        if (c + NSTG - 1 < NCH) LOAD_STAGE(c + NSTG - 1, sl);
        cp_commit();

        const uint32_t so = (uint32_t)sc * STG_;
#pragma unroll
        for (int ks = 0; ks < 2; ks++){
            const uint32_t kx = (uint32_t)(ks << 5);
            uint32_t ah[4][4], al[4][4];
#pragma unroll
            for (int i = 0; i < 4; i++){
                ldsm_x4(ah[i], ((aoff + so +       (uint32_t)(i*1024))) ^ kx);
                ldsm_x4(al[i], ((aoff + so + ARR + (uint32_t)(i*1024))) ^ kx);
            }
            uint32_t bh[2][4], bl2[2][4];
#pragma unroll
            for (int jp = 0; jp < 2; jp++){
                ldsm_x4(bh[jp], ((boff + so + (uint32_t)(jp*1024))) ^ kx);
                if (MODE == 3)
                    ldsm_x4(bl2[jp], ((boff + so + ARR + (uint32_t)(jp*1024))) ^ kx);
            }
#pragma unroll
            for (int i = 0; i < 4; i++){
#pragma unroll
                for (int j = 0; j < 4; j++){
                    uint32_t bfh[2] = { bh[j>>1][j&1], bh[j>>1][2+(j&1)] };
                    mma16816(acc[i][j], ah[i], bfh);
                    mma16816(acc[i][j], al[i], bfh);
                    if (MODE == 3){
                        uint32_t bfl[2] = { bl2[j>>1][j&1], bl2[j>>1][2+(j&1)] };
                        mma16816(acc[i][j], ah[i], bfl);
                    }
                }
            }
        }
        sc = (sc == NSTG-1) ? 0 : sc + 1;
        sl = (sl == NSTG-1) ? 0 : sl + 1;
    }
    #undef LOAD_STAGE

    float* Cb; int n0; int ld;
    if (MODE == 1){
        if (bn < DI){ Cb = g_xc; n0 = bn; } else { Cb = g_z; n0 = bn - DI; }
        ld = DI;
    } else { Cb = C; n0 = bn; ld = ldc; }

    const int g = lane >> 2, t = lane & 3;
#pragma unroll
    for (int i = 0; i < 4; i++){
        const int r0 = bm + wm*64 + i*16 + g;
#pragma unroll
        for (int j = 0; j < 4; j++){
            const int col = n0 + wn*32 + j*8 + t*2;
            float v0 = acc[i][j][0], v1 = acc[i][j][1];
            float v2 = acc[i][j][2], v3 = acc[i][j][3];
            if (MODE == 3){
                float b0 = bias[col], b1 = bias[col+1];
                v0 += b0; v1 += b1; v2 += b0; v3 += b1;
                v0 = (v0 > 20.f) ? v0 : log1pf(__expf(v0));
                v1 = (v1 > 20.f) ? v1 : log1pf(__expf(v1));
                v2 = (v2 > 20.f) ? v2 : log1pf(__expf(v2));
                v3 = (v3 > 20.f) ? v3 : log1pf(__expf(v3));
            }
            *(float2*)(Cb + (size_t)r0       * ld + col) = make_float2(v0, v1);
            *(float2*)(Cb + (size_t)(r0 + 8) * ld + col) = make_float2(v2, v3);
        }
    }
}

#define MMA_SMEM_MAIN  (4*3*ARR + 1024)   // 99328
#define MMA_SMEM_DELTA (2*4*ARR + 1024)   // 66560

// ---------------- prep: all input conversions + dBC zero, one launch ----------
__device__ __forceinline__ void dev_split4(const float* in, __half* hi, __half* lo,
                                           int blk, int n4)
{
    int i0 = blk * 1024 + threadIdx.x;
    #pragma unroll
    for (int k = 0; k < 4; k++){
        int i = i0 + k * 256;
        if (i >= n4) continue;
        float4 v = ((const float4*)in)[i];
        float a[4] = {v.x, v.y, v.z, v.w};
        __half h[4], l[4];
        #pragma unroll
        for (int q = 0; q < 4; q++){
            h[q] = __float2half_rn(a[q]);
            l[q] = __float2half_rn(a[q] - __half2float(h[q]));
        }
        ((__half2*)hi)[2*i]   = __halves2half2(h[0], h[1]);
        ((__half2*)hi)[2*i+1] = __halves2half2(h[2], h[3]);
        ((__half2*)lo)[2*i]   = __halves2half2(l[0], l[1]);
        ((__half2*)lo)[2*i+1] = __halves2half2(l[2], l[3]);
    }
}
__device__ __forceinline__ void dev_cvt4(const float* in, __half* out, int blk, int n4)
{
    int i0 = blk * 1024 + threadIdx.x;
    #pragma unroll
    for (int k = 0; k < 4; k++){
        int i = i0 + k * 256;
        if (i >= n4) continue;
        float4 v = ((const float4*)in)[i];
        ((__half2*)out)[2*i]   = __halves2half2(__float2half_rn(v.x), __float2half_rn(v.y));
        ((__half2*)out)[2*i+1] = __halves2half2(__float2half_rn(v.z), __float2half_rn(v.w));
    }
}
__global__ __launch_bounds__(256)
void prep_kernel(const float* __restrict__ x, const float* __restrict__ W_in,
                 const float* __restrict__ W_out, const float* __restrict__ W_dt)
{
    const int b = blockIdx.x;
    if (b < 512){
        dev_split4(x, g_xh, g_xl, b, BL*DM/4);
    } else if (b < 1536){
        dev_cvt4(W_in, g_wih, b - 512, 2*DI*DM/4);
    } else if (b < 2048){
        dev_cvt4(W_out, g_woh, b - 1536, DM*DI/4);
    } else if (b < 2080){
        dev_split4(W_dt, g_wdh, g_wdl, b - 2048, DI*DTR/4);
    } else {
        int i0 = (b - 2080) * 1024 + threadIdx.x;
        #pragma unroll
        for (int k = 0; k < 4; k++){
            int i = i0 + k * 256;
            if (i < BL*96/4)
                ((float4*)g_dBC)[i] = make_float4(0.f, 0.f, 0.f, 0.f);
        }
    }
}
#define PREP_BLOCKS 2128

// ------ split of dBC[:, 0:64] (row stride 96) into packed [BL,64] hi/lo -------
__global__ __launch_bounds__(256)
void split_dbc(void)
{
    int i = blockIdx.x * blockDim.x + threadIdx.x;   // over BL*16 float4s
    if (i >= BL * 16) return;
    int row = i >> 4, c4 = i & 15;
    float4 v = *(const float4*)(g_dBC + (size_t)row * 96 + c4 * 4);
    float a[4] = {v.x, v.y, v.z, v.w};
    __half h[4], l[4];
    #pragma unroll
    for (int k = 0; k < 4; k++){
        h[k] = __float2half_rn(a[k]);
        l[k] = __float2half_rn(a[k] - __half2float(h[k]));
    }
    size_t o = (size_t)row * 64 + c4 * 4;
    ((__half2*)(g_dch + o))[0] = __halves2half2(h[0], h[1]);
    ((__half2*)(g_dch + o))[1] = __halves2half2(h[2], h[3]);
    ((__half2*)(g_dcl + o))[0] = __halves2half2(l[0], l[1]);
    ((__half2*)(g_dcl + o))[1] = __halves2half2(l[2], l[3]);
}

// ------- small GEMM v2: 32x96 tile, split-K=4, atomic accumulate --------------
#define SKS 4
__global__ __launch_bounds__(256)
void gemm_small2(const float* __restrict__ A, int lda,
                 const float* __restrict__ W, int Kdim,
                 float* __restrict__ C, int ldc)
{
    const int bm = blockIdx.y * 32;
    const int k0 = blockIdx.x * (Kdim / SKS);
    const int k1 = k0 + Kdim / SKS;

    __shared__ float As[32][33];
    __shared__ float Ws[32][97];

    float acc[2][6];
#pragma unroll
    for (int i = 0; i < 2; i++)
#pragma unroll
        for (int j = 0; j < 6; j++) acc[i][j] = 0.f;

    const int tid  = threadIdx.x;
    const int lrow = tid >> 3;
    const int lcol = (tid & 7) * 4;
    const int tm   = (tid >> 4) * 2;
    const int tn   = (tid & 15) * 6;

    for (int kt = k0; kt < k1; kt += 32) {
        float4 av = *(const float4*)(A + (size_t)(bm + lrow) * lda + kt + lcol);
        As[lcol+0][lrow] = av.x; As[lcol+1][lrow] = av.y;
        As[lcol+2][lrow] = av.z; As[lcol+3][lrow] = av.w;
        #pragma unroll
        for (int q = 0; q < 3; q++){
            int idx  = tid + q * 256;
            int wrow = idx >> 3;
            int wc4  = (idx & 7) * 4;
            float4 wv = *(const float4*)(W + (size_t)wrow * Kdim + kt + wc4);
            Ws[wc4+0][wrow] = wv.x; Ws[wc4+1][wrow] = wv.y;
            Ws[wc4+2][wrow] = wv.z; Ws[wc4+3][wrow] = wv.w;
        }
        __syncthreads();

#pragma unroll
        for (int kk = 0; kk < 32; kk++) {
            float a0 = As[kk][tm], a1 = As[kk][tm+1];
            float b[6];
            #pragma unroll
            for (int j = 0; j < 6; j++) b[j] = Ws[kk][tn+j];
            #pragma unroll
            for (int j = 0; j < 6; j++){
                acc[0][j] = fmaf(a0, b[j], acc[0][j]);
                acc[1][j] = fmaf(a1, b[j], acc[1][j]);
            }
        }
        __syncthreads();
    }

#pragma unroll
    for (int i = 0; i < 2; i++)
#pragma unroll
        for (int j = 0; j < 6; j++)
            atomicAdd(C + (size_t)(bm + tm + i) * ldc + (tn + j), acc[i][j]);
}

// ------- depthwise causal conv + bias + SiLU: 4 outputs/thread ----------------
__global__ __launch_bounds__(256)
void conv_silu_kernel(const float* __restrict__ cw, const float* __restrict__ cb)
{
    int i = blockIdx.x * blockDim.x + threadIdx.x;
    if (i >= BL * DI / 4) return;
    const int d4 = (i % (DI/4)) * 4;
    const int bl = i / (DI/4);
    const int l  = bl % L_;
    const int b  = bl / L_;

    float4 s = *(const float4*)(cb + d4);
    float4 W0 = *(const float4*)(cw + (d4+0)*4);
    float4 W1 = *(const float4*)(cw + (d4+1)*4);
    float4 W2 = *(const float4*)(cw + (d4+2)*4);
    float4 W3 = *(const float4*)(cw + (d4+3)*4);

    const float* base = g_xc + (size_t)b * L_ * DI + d4;
    float4 v[KC];
#pragma unroll
    for (int j = 0; j < KC; j++){
        int ll = l + j - (KC - 1);
        v[j] = (ll >= 0) ? *(const float4*)(base + (size_t)ll * DI)
                         : make_float4(0.f, 0.f, 0.f, 0.f);
    }
    s.x = fmaf(v[0].x, W0.x, s.x); s.x = fmaf(v[1].x, W0.y, s.x);
    s.x = fmaf(v[2].x, W0.z, s.x); s.x = fmaf(v[3].x, W0.w, s.x);
    s.y = fmaf(v[0].y, W1.x, s.y); s.y = fmaf(v[1].y, W1.y, s.y);
    s.y = fmaf(v[2].y, W1.z, s.y); s.y = fmaf(v[3].y, W1.w, s.y);
    s.z = fmaf(v[0].z, W2.x, s.z); s.z = fmaf(v[1].z, W2.y, s.z);
    s.z = fmaf(v[2].z, W2.z, s.z); s.z = fmaf(v[3].z, W2.w, s.z);
    s.w = fmaf(v[0].w, W3.x, s.w); s.w = fmaf(v[1].w, W3.y, s.w);
    s.w = fmaf(v[2].w, W3.z, s.w); s.w = fmaf(v[3].w, W3.w, s.w);

    float4 o;
    o.x = s.x / (1.f + __expf(-s.x));
    o.y = s.y / (1.f + __expf(-s.y));
    o.z = s.z / (1.f + __expf(-s.z));
    o.w = s.w / (1.f + __expf(-s.w));
    *(float4*)(g_xca + (size_t)bl * DI + d4) = o;
}

// ============== chunked scan: phase A ========================================
__global__ __launch_bounds__(64)
void scanA(const float* __restrict__ A_log)
{
    const int gwarp = blockIdx.x * 2 + (threadIdx.x >> 5);
    const int chunk = gwarp & (SC_NCH - 1);
    const int wpair = gwarp >> 4;
    const int lane  = threadIdx.x & 31;
    const int half  = lane >> 4;
    const int n     = lane & 15;
    const int c     = wpair * 2 + half;
    const int b     = c / DI;
    const int d     = c % DI;

    const float Aval = -__expf(A_log[d * DS + n]);

    const size_t rbase = (size_t)b * L_ * DI + d;
    const float* pD = g_del + rbase;
    const float* pX = g_xca + rbase;
    const float* pB = g_dBC + (size_t)b * L_ * 96 + DTR + n;

    float h = 0.f, P = 1.f;
    const int l0 = chunk * SC_CL;
    for (int q = 0; q < SC_CL; q++){
        const size_t l = (size_t)(l0 + q);
        float dlt = pD[l * DI];
        float xv  = pX[l * DI];
        float Bn  = pB[l * 96];
        float a = __expf(dlt * Aval);
        h = fmaf(a, h, dlt * Bn * xv);
        P *= a;
    }
    const size_t o = ((size_t)c * SC_NCH + chunk) * DS + n;
    g_hend [o] = h;
    g_aprod[o] = P;
}

// ============== chunked scan: phase B ========================================
__global__ __launch_bounds__(256)
void scanB(void)
{
    const int idx = blockIdx.x * 256 + threadIdx.x;
    if (idx >= B_ * DI * DS) return;
    const int c = idx >> 4;
    const int n = idx & 15;

    float h0 = 0.f;
#pragma unroll
    for (int j = 0; j < SC_NCH; j++){
        const size_t o = ((size_t)c * SC_NCH + j) * DS + n;
        g_h0[o] = h0;
        h0 = fmaf(g_aprod[o], h0, g_hend[o]);
    }
}

// ============== chunked scan: phase C ========================================
__global__ __launch_bounds__(64)
void scanC(const float* __restrict__ A_log, const float* __restrict__ Dp)
{
    const int gwarp = blockIdx.x * 2 + (threadIdx.x >> 5);
    const int chunk = gwarp & (SC_NCH - 1);
    const int wpair = gwarp >> 4;
    const int lane  = threadIdx.x & 31;
    const int half  = lane >> 4;
    const int n     = lane & 15;
    const int c     = wpair * 2 + half;
    const int b     = c / DI;
    const int d     = c % DI;

    const float Aval = -__expf(A_log[d * DS + n]);
    const float dp   = Dp[d];

    const size_t rbase = (size_t)b * L_ * DI + d;
    const float* pD = g_del + rbase;
    const float* pX = g_xca + rbase;
    const float* pZ = g_z   + rbase;
    const float* pB = g_dBC + (size_t)b * L_ * 96 + DTR + n;
    const float* pC = g_dBC + (size_t)b * L_ * 96 + DTR + DS + n;
    __half* pUh = g_uh + rbase;
    __half* pUl = g_ul + rbase;

    float h = g_h0[((size_t)c * SC_NCH + chunk) * DS + n];

    const int l0 = chunk * SC_CL;
    for (int q = 0; q < SC_CL; q++){
        const size_t l = (size_t)(l0 + q);
        float dlt = pD[l * DI];
        float xv  = pX[l * DI];
        float zv  = pZ[l * DI];
        float Bn  = pB[l * 96];
        float Cn  = pC[l * 96];

        float a = __expf(dlt * Aval);
        h = fmaf(a, h, dlt * Bn * xv);
        float p = h * Cn;
        p += __shfl_xor_sync(0xffffffffu, p, 8);
        p += __shfl_xor_sync(0xffffffffu, p, 4);
        p += __shfl_xor_sync(0xffffffffu, p, 2);
        p += __shfl_xor_sync(0xffffffffu, p, 1);
        if (n == 0){
            float y  = fmaf(dp, xv, p);
            float sz = zv / (1.f + __expf(-zv));
            float u  = y * sz;
            __half uh = __float2half_rn(u);
            __half ul = __float2half_rn(u - __half2float(uh));
            pUh[l * DI] = uh;
            pUl[l * DI] = ul;
        }
    }
}

// ---------------- launch ------------------------------------------------------
extern "C" void kernel_launch(void* const* d_in, const int* in_sizes, int n_in,
                              void* d_out, int out_size)
{
    const float* x      = (const float*)d_in[0];
    const float* W_in   = (const float*)d_in[1];
    const float* conv_w = (const float*)d_in[2];
    const float* conv_b = (const float*)d_in[3];
    const float* W_x    = (const float*)d_in[4];
    const float* W_dt   = (const float*)d_in[5];
    const float* b_dt   = (const float*)d_in[6];
    const float* A_log  = (const float*)d_in[7];
    const float* Dp     = (const float*)d_in[8];
    const float* W_out  = (const float*)d_in[9];
    float* out = (float*)d_out;

    float* p_xca; cudaGetSymbolAddress((void**)&p_xca, g_xca);
    float* p_dBC; cudaGetSymbolAddress((void**)&p_dBC, g_dBC);
    float* p_del; cudaGetSymbolAddress((void**)&p_del, g_del);

    __half *p_xh, *p_xl, *p_wih, *p_uh, *p_ul, *p_woh, *p_dch, *p_dcl, *p_wdh, *p_wdl;
    cudaGetSymbolAddress((void**)&p_xh,  g_xh);
    cudaGetSymbolAddress((void**)&p_xl,  g_xl);
    cudaGetSymbolAddress((void**)&p_wih, g_wih);
    cudaGetSymbolAddress((void**)&p_uh,  g_uh);
    cudaGetSymbolAddress((void**)&p_ul,  g_ul);
    cudaGetSymbolAddress((void**)&p_woh, g_woh);
    cudaGetSymbolAddress((void**)&p_dch, g_dch);
    cudaGetSymbolAddress((void**)&p_dcl, g_dcl);
    cudaGetSymbolAddress((void**)&p_wdh, g_wdh);
    cudaGetSymbolAddress((void**)&p_wdl, g_wdl);

    cudaFuncSetAttribute(mma_gemm<0>, cudaFuncAttributeMaxDynamicSharedMemorySize, MMA_SMEM_MAIN);
    cudaFuncSetAttribute(mma_gemm<1>, cudaFuncAttributeMaxDynamicSharedMemorySize, MMA_SMEM_MAIN);
    cudaFuncSetAttribute(mma_gemm<3>, cudaFuncAttributeMaxDynamicSharedMemorySize, MMA_SMEM_DELTA);

    // 1) prep: split x, cvt W_in, cvt W_out, split W_dt, zero dBC (one launch)
    prep_kernel<<<PREP_BLOCKS, 256>>>(x, W_in, W_out, W_dt);

    // 2) xz = x @ W_in^T  (HMMA fp16x2) -> g_xc / g_z
    {
        dim3 grid(2 * DI / 128, BL / 128);
        mma_gemm<1><<<grid, 256, MMA_SMEM_MAIN>>>(p_xh, p_xl, p_wih, nullptr, nullptr,
                                                  DM, DM, nullptr, 0);
    }
    // 3) depthwise causal conv + bias + silu -> g_xca
    {
        int total = BL * DI / 4;
        conv_silu_kernel<<<(total + 255) / 256, 256>>>(conv_w, conv_b);
    }
    // 4) dBC = xca @ W_x^T  (32x96 tile, split-K=4, atomic)   <- profiled slot
    {
        dim3 grid(SKS, BL / 32);
        gemm_small2<<<grid, 256>>>(p_xca, DI, W_x, DI, p_dBC, 96);
    }
    // 5) split dBC[:, :64] into fp16 hi/lo
    {
        split_dbc<<<(BL * 16 + 255) / 256, 256>>>();
    }
    // 6) delta = softplus(dBC[:, :64] @ W_dt^T + b_dt)  (HMMA fp16x3, K=64)
    {
        dim3 grid(DI / 128, BL / 128);
        mma_gemm<3><<<grid, 256, MMA_SMEM_DELTA>>>(p_dch, p_dcl, p_wdh, p_wdl, b_dt,
                                                   DTR, DTR, p_del, DI);
    }
    // 7) chunked selective scan
    {
        int nwarps = (B_ * DI / 2) * SC_NCH;
        scanA<<<nwarps / 2, 64>>>(A_log);
        scanB<<<(B_ * DI * DS + 255) / 256, 256>>>();
        scanC<<<nwarps / 2, 64>>>(A_log, Dp);
    }
    // 8) out = u @ W_out^T  (HMMA fp16x2)
    {
        dim3 grid(DM / 128, BL / 128);
        mma_gemm<0><<<grid, 256, MMA_SMEM_MAIN>>>(p_uh, p_ul, p_woh, nullptr, nullptr,
                                                  DI, DI, out, DM);
    }
}

// round 16
// speedup vs baseline: 1.3326x; 1.0073x over previous
#include <cuda_runtime.h>
#include <cuda_fp16.h>
#include <math.h>
#include <stdint.h>

// Problem constants
#define B_  2
#define L_  1024
#define DM  1024
#define DI  2048
#define DS  16
#define DTR 64
#define KC  4
#define BL  (B_*L_)   // 2048

// scan chunking
#define SC_NCH 16
#define SC_CL  (L_/SC_NCH)  // 64

// ---------------- scratch (device globals) -----------------------------------
__device__ float g_xc [BL*DI];
__device__ float g_z  [BL*DI];
__device__ float g_xca[BL*DI];
__device__ float g_dBC[BL*96];
__device__ float g_del[BL*DI];

__device__ float g_hend [B_*DI*SC_NCH*DS];
__device__ float g_aprod[B_*DI*SC_NCH*DS];
__device__ float g_h0   [B_*DI*SC_NCH*DS];

__device__ __half g_xh [BL*DM];
__device__ __half g_xl [BL*DM];
__device__ __half g_wih[2*DI*DM];
__device__ __half g_uh [BL*DI];
__device__ __half g_ul [BL*DI];
__device__ __half g_woh[DM*DI];
__device__ __half g_dch[BL*DTR];
__device__ __half g_dcl[BL*DTR];
__device__ __half g_wdh[DI*DTR];
__device__ __half g_wdl[DI*DTR];

// ======================= PTX helpers (sm_80 baseline) =========================
__device__ __forceinline__ uint32_t smem_u32(const void* p){
    uint32_t a;
    asm("{ .reg .u64 t; cvta.to.shared.u64 t, %1; cvt.u32.u64 %0, t; }" : "=r"(a) : "l"(p));
    return a;
}
__device__ __forceinline__ void cp16(uint32_t dst, const void* src){
    asm volatile("cp.async.cg.shared.global [%0], [%1], 16;" :: "r"(dst), "l"(src));
}
__device__ __forceinline__ void cp_commit(){ asm volatile("cp.async.commit_group;" ::: "memory"); }
template<int N> __device__ __forceinline__ void cp_wait(){
    asm volatile("cp.async.wait_group %0;" :: "n"(N) : "memory");
}
__device__ __forceinline__ void ldsm_x4(uint32_t* r, uint32_t addr){
    asm volatile("ldmatrix.sync.aligned.m8n8.x4.shared.b16 {%0,%1,%2,%3}, [%4];"
        : "=r"(r[0]), "=r"(r[1]), "=r"(r[2]), "=r"(r[3]) : "r"(addr));
}
__device__ __forceinline__ void mma16816(float* c, const uint32_t* a, const uint32_t* b){
    asm volatile(
        "mma.sync.aligned.m16n8k16.row.col.f32.f16.f16.f32 "
        "{%0,%1,%2,%3}, {%4,%5,%6,%7}, {%8,%9}, {%0,%1,%2,%3};"
        : "+f"(c[0]), "+f"(c[1]), "+f"(c[2]), "+f"(c[3])
        : "r"(a[0]), "r"(a[1]), "r"(a[2]), "r"(a[3]), "r"(b[0]), "r"(b[1]));
}

// ===== HMMA GEMM: 128x128 CTA, 8 warps, warp 64x32, XOR-swizzled cp.async =====
// MODE 0: fp16x2 plain store.  MODE 1: fp16x2, split g_xc/g_z at DI.
// MODE 3: fp16x3 (4 arrays, 2 stages), bias+softplus epilogue (delta GEMM).
#define ARR (128*64)

template<int MODE>
__global__ __launch_bounds__(256, 2)
void mma_gemm(const __half* __restrict__ Ah, const __half* __restrict__ Al,
              const __half* __restrict__ Bh, const __half* __restrict__ Bl,
              const float* __restrict__ bias,
              int Klen, int lda, float* __restrict__ C, int ldc)
{
    constexpr int NARR  = (MODE == 3) ? 4 : 3;
    constexpr int NSTG  = (MODE == 3) ? 2 : 4;
    constexpr int STG_  = NARR * ARR;
    constexpr int WAITN = NSTG - 2;

    extern __shared__ char sraw[];
    const uint32_t base = (smem_u32(sraw) + 1023) & ~1023u;

    const int tid  = threadIdx.x;
    const int wid  = tid >> 5, lane = tid & 31;
    const int wm   = wid & 1;
    const int wn   = wid >> 1;
    const int bm   = blockIdx.y * 128, bn = blockIdx.x * 128;

    float acc[4][4][4];
#pragma unroll
    for (int i = 0; i < 4; i++)
#pragma unroll
        for (int j = 0; j < 4; j++)
#pragma unroll
            for (int q = 0; q < 4; q++) acc[i][j][q] = 0.f;

    const int  row   = tid >> 1;
    const int  hs    = tid & 1;
    const int  rowsw = (row >> 1) & 3;
    const uint32_t c0 = (uint32_t)(((2*hs)     ^ rowsw) << 4);
    const uint32_t c1 = (uint32_t)(((2*hs + 1) ^ rowsw) << 4);
    const char* sAh = (const char*)(Ah + (size_t)(bm + row) * lda) + hs*32;
    const char* sAl = (const char*)(Al + (size_t)(bm + row) * lda) + hs*32;
    const char* sBh = (const char*)(Bh + (size_t)(bn + row) * lda) + hs*32;
    const char* sBl = (MODE == 3) ? (const char*)(Bl + (size_t)(bn + row) * lda) + hs*32 : nullptr;
    const uint32_t dst0 = base + row*64;

    #define LOAD_STAGE(c, st) do {                                          \
        uint32_t d = dst0 + (st)*STG_;                                       \
        size_t   g = (size_t)(c)*64;                                         \
        cp16(d +         c0, sAh+g); cp16(d +         c1, sAh+g+16);         \
        cp16(d + ARR   + c0, sAl+g); cp16(d + ARR   + c1, sAl+g+16);         \
        cp16(d + 2*ARR + c0, sBh+g); cp16(d + 2*ARR + c1, sBh+g+16);         \
        if (MODE == 3){                                                      \
            cp16(d + 3*ARR + c0, sBl+g); cp16(d + 3*ARR + c1, sBl+g+16);     \
        }                                                                    \
    } while(0)

    const int NCH = Klen >> 5;
#pragma unroll
    for (int p = 0; p < NSTG - 1; p++){
        if (p < NCH) LOAD_STAGE(p, p);
        cp_commit();
    }

    const int r15 = lane & 15;
    const int lch = lane >> 4;
    const int lsw = (r15 >> 1) & 3;
    const uint32_t apc = (uint32_t)((lch ^ lsw) << 4);
    const uint32_t aoff = base + (uint32_t)((wm*64 + r15)*64) + apc;
    const uint32_t boff = base + 2*ARR + (uint32_t)((wn*32 + r15)*64) + apc;

    int sc = 0, sl = NSTG - 1;
    for (int c = 0; c < NCH; c++){
        cp_wait<WAITN>();
        __syncthreads();

        if (c + NSTG - 1 < NCH) LOAD_STAGE(c + NSTG - 1, sl);
        cp_commit();

        const uint32_t so = (uint32_t)sc * STG_;
#pragma unroll
        for (int ks = 0; ks < 2; ks++){
            const uint32_t kx = (uint32_t)(ks << 5);
            uint32_t ah[4][4], al[4][4];
#pragma unroll
            for (int i = 0; i < 4; i++){
                ldsm_x4(ah[i], ((aoff + so +       (uint32_t)(i*1024))) ^ kx);
                ldsm_x4(al[i], ((aoff + so + ARR + (uint32_t)(i*1024))) ^ kx);
            }
            uint32_t bh[2][4], bl2[2][4];
#pragma unroll
            for (int jp = 0; jp < 2; jp++){
                ldsm_x4(bh[jp], ((boff + so + (uint32_t)(jp*1024))) ^ kx);
                if (MODE == 3)
                    ldsm_x4(bl2[jp], ((boff + so + ARR + (uint32_t)(jp*1024))) ^ kx);
            }
#pragma unroll
            for (int i = 0; i < 4; i++){
#pragma unroll
                for (int j = 0; j < 4; j++){
                    uint32_t bfh[2] = { bh[j>>1][j&1], bh[j>>1][2+(j&1)] };
                    mma16816(acc[i][j], ah[i], bfh);
                    mma16816(acc[i][j], al[i], bfh);
                    if (MODE == 3){
                        uint32_t bfl[2] = { bl2[j>>1][j&1], bl2[j>>1][2+(j&1)] };
                        mma16816(acc[i][j], ah[i], bfl);
                    }
                }
            }
        }
        sc = (sc == NSTG-1) ? 0 : sc + 1;
        sl = (sl == NSTG-1) ? 0 : sl + 1;
    }
    #undef LOAD_STAGE

    float* Cb; int n0; int ld;
    if (MODE == 1){
        if (bn < DI){ Cb = g_xc; n0 = bn; } else { Cb = g_z; n0 = bn - DI; }
        ld = DI;
    } else { Cb = C; n0 = bn; ld = ldc; }

    const int g = lane >> 2, t = lane & 3;
#pragma unroll
    for (int i = 0; i < 4; i++){
        const int r0 = bm + wm*64 + i*16 + g;
#pragma unroll
        for (int j = 0; j < 4; j++){
            const int col = n0 + wn*32 + j*8 + t*2;
            float v0 = acc[i][j][0], v1 = acc[i][j][1];
            float v2 = acc[i][j][2], v3 = acc[i][j][3];
            if (MODE == 3){
                float b0 = bias[col], b1 = bias[col+1];
                v0 += b0; v1 += b1; v2 += b0; v3 += b1;
                v0 = (v0 > 20.f) ? v0 : log1pf(__expf(v0));
                v1 = (v1 > 20.f) ? v1 : log1pf(__expf(v1));
                v2 = (v2 > 20.f) ? v2 : log1pf(__expf(v2));
                v3 = (v3 > 20.f) ? v3 : log1pf(__expf(v3));
            }
            *(float2*)(Cb + (size_t)r0       * ld + col) = make_float2(v0, v1);
            *(float2*)(Cb + (size_t)(r0 + 8) * ld + col) = make_float2(v2, v3);
        }
    }
}

#define MMA_SMEM_MAIN  (4*3*ARR + 1024)   // 99328
#define MMA_SMEM_DELTA (2*4*ARR + 1024)   // 66560

// ---------------- prep: all input conversions + dBC zero, one launch ----------
__device__ __forceinline__ void dev_split4(const float* in, __half* hi, __half* lo,
                                           int blk, int n4)
{
    int i0 = blk * 1024 + threadIdx.x;
    #pragma unroll
    for (int k = 0; k < 4; k++){
        int i = i0 + k * 256;
        if (i >= n4) continue;
        float4 v = ((const float4*)in)[i];
        float a[4] = {v.x, v.y, v.z, v.w};
        __half h[4], l[4];
        #pragma unroll
        for (int q = 0; q < 4; q++){
            h[q] = __float2half_rn(a[q]);
            l[q] = __float2half_rn(a[q] - __half2float(h[q]));
        }
        ((__half2*)hi)[2*i]   = __halves2half2(h[0], h[1]);
        ((__half2*)hi)[2*i+1] = __halves2half2(h[2], h[3]);
        ((__half2*)lo)[2*i]   = __halves2half2(l[0], l[1]);
        ((__half2*)lo)[2*i+1] = __halves2half2(l[2], l[3]);
    }
}
__device__ __forceinline__ void dev_cvt4(const float* in, __half* out, int blk, int n4)
{
    int i0 = blk * 1024 + threadIdx.x;
    #pragma unroll
    for (int k = 0; k < 4; k++){
        int i = i0 + k * 256;
        if (i >= n4) continue;
        float4 v = ((const float4*)in)[i];
        ((__half2*)out)[2*i]   = __halves2half2(__float2half_rn(v.x), __float2half_rn(v.y));
        ((__half2*)out)[2*i+1] = __halves2half2(__float2half_rn(v.z), __float2half_rn(v.w));
    }
}
__global__ __launch_bounds__(256)
void prep_kernel(const float* __restrict__ x, const float* __restrict__ W_in,
                 const float* __restrict__ W_out, const float* __restrict__ W_dt)
{
    const int b = blockIdx.x;
    if (b < 512){
        dev_split4(x, g_xh, g_xl, b, BL*DM/4);
    } else if (b < 1536){
        dev_cvt4(W_in, g_wih, b - 512, 2*DI*DM/4);
    } else if (b < 2048){
        dev_cvt4(W_out, g_woh, b - 1536, DM*DI/4);
    } else if (b < 2080){
        dev_split4(W_dt, g_wdh, g_wdl, b - 2048, DI*DTR/4);
    } else {
        int i0 = (b - 2080) * 1024 + threadIdx.x;
        #pragma unroll
        for (int k = 0; k < 4; k++){
            int i = i0 + k * 256;
            if (i < BL*96/4)
                ((float4*)g_dBC)[i] = make_float4(0.f, 0.f, 0.f, 0.f);
        }
    }
}
#define PREP_BLOCKS 2128

// ------ split of dBC[:, 0:64] (row stride 96) into packed [BL,64] hi/lo -------
__global__ __launch_bounds__(256)
void split_dbc(void)
{
    int i = blockIdx.x * blockDim.x + threadIdx.x;
    if (i >= BL * 16) return;
    int row = i >> 4, c4 = i & 15;
    float4 v = *(const float4*)(g_dBC + (size_t)row * 96 + c4 * 4);
    float a[4] = {v.x, v.y, v.z, v.w};
    __half h[4], l[4];
    #pragma unroll
    for (int k = 0; k < 4; k++){
        h[k] = __float2half_rn(a[k]);
        l[k] = __float2half_rn(a[k] - __half2float(h[k]));
    }
    size_t o = (size_t)row * 64 + c4 * 4;
    ((__half2*)(g_dch + o))[0] = __halves2half2(h[0], h[1]);
    ((__half2*)(g_dch + o))[1] = __halves2half2(h[2], h[3]);
    ((__half2*)(g_dcl + o))[0] = __halves2half2(l[0], l[1]);
    ((__half2*)(g_dcl + o))[1] = __halves2half2(l[2], l[3]);
}

// ------- small GEMM v3: 64x96 tile, acc 4x6, split-K=8, atomic accumulate -----
#define SKS 8
__global__ __launch_bounds__(256)
void gemm_small3(const float* __restrict__ A, int lda,
                 const float* __restrict__ W, int Kdim,
                 float* __restrict__ C, int ldc)
{
    const int bm = blockIdx.y * 64;
    const int k0 = blockIdx.x * (Kdim / SKS);      // slice of 256
    const int k1 = k0 + Kdim / SKS;

    __shared__ float As[32][65];
    __shared__ float Ws[32][97];

    float acc[4][6];
#pragma unroll
    for (int i = 0; i < 4; i++)
#pragma unroll
        for (int j = 0; j < 6; j++) acc[i][j] = 0.f;

    const int tid  = threadIdx.x;
    const int arow = tid >> 2;          // 0..63
    const int acol = (tid & 3) * 8;     // 0,8,16,24
    const int tm   = (tid >> 4) * 4;    // 0..60
    const int tn   = (tid & 15) * 6;    // 0..90

    for (int kt = k0; kt < k1; kt += 32) {
        float4 a0 = *(const float4*)(A + (size_t)(bm + arow) * lda + kt + acol);
        float4 a1 = *(const float4*)(A + (size_t)(bm + arow) * lda + kt + acol + 4);
        As[acol+0][arow] = a0.x; As[acol+1][arow] = a0.y;
        As[acol+2][arow] = a0.z; As[acol+3][arow] = a0.w;
        As[acol+4][arow] = a1.x; As[acol+5][arow] = a1.y;
        As[acol+6][arow] = a1.z; As[acol+7][arow] = a1.w;
        #pragma unroll
        for (int q = 0; q < 3; q++){
            int idx  = tid + q * 256;      // 0..767
            int wrow = idx >> 3;           // 0..95
            int wc4  = (idx & 7) * 4;
            float4 wv = *(const float4*)(W + (size_t)wrow * Kdim + kt + wc4);
            Ws[wc4+0][wrow] = wv.x; Ws[wc4+1][wrow] = wv.y;
            Ws[wc4+2][wrow] = wv.z; Ws[wc4+3][wrow] = wv.w;
        }
        __syncthreads();

#pragma unroll
        for (int kk = 0; kk < 32; kk++) {
            float a[4], b[6];
            #pragma unroll
            for (int i = 0; i < 4; i++) a[i] = As[kk][tm+i];
            #pragma unroll
            for (int j = 0; j < 6; j++) b[j] = Ws[kk][tn+j];
            #pragma unroll
            for (int i = 0; i < 4; i++)
                #pragma unroll
                for (int j = 0; j < 6; j++)
                    acc[i][j] = fmaf(a[i], b[j], acc[i][j]);
        }
        __syncthreads();
    }

#pragma unroll
    for (int i = 0; i < 4; i++)
#pragma unroll
        for (int j = 0; j < 6; j++)
            atomicAdd(C + (size_t)(bm + tm + i) * ldc + (tn + j), acc[i][j]);
}

// ------- depthwise causal conv + bias + SiLU: 4 outputs/thread ----------------
__global__ __launch_bounds__(256)
void conv_silu_kernel(const float* __restrict__ cw, const float* __restrict__ cb)
{
    int i = blockIdx.x * blockDim.x + threadIdx.x;
    if (i >= BL * DI / 4) return;
    const int d4 = (i % (DI/4)) * 4;
    const int bl = i / (DI/4);
    const int l  = bl % L_;
    const int b  = bl / L_;

    float4 s = *(const float4*)(cb + d4);
    float4 W0 = *(const float4*)(cw + (d4+0)*4);
    float4 W1 = *(const float4*)(cw + (d4+1)*4);
    float4 W2 = *(const float4*)(cw + (d4+2)*4);
    float4 W3 = *(const float4*)(cw + (d4+3)*4);

    const float* base = g_xc + (size_t)b * L_ * DI + d4;
    float4 v[KC];
#pragma unroll
    for (int j = 0; j < KC; j++){
        int ll = l + j - (KC - 1);
        v[j] = (ll >= 0) ? *(const float4*)(base + (size_t)ll * DI)
                         : make_float4(0.f, 0.f, 0.f, 0.f);
    }
    s.x = fmaf(v[0].x, W0.x, s.x); s.x = fmaf(v[1].x, W0.y, s.x);
    s.x = fmaf(v[2].x, W0.z, s.x); s.x = fmaf(v[3].x, W0.w, s.x);
    s.y = fmaf(v[0].y, W1.x, s.y); s.y = fmaf(v[1].y, W1.y, s.y);
    s.y = fmaf(v[2].y, W1.z, s.y); s.y = fmaf(v[3].y, W1.w, s.y);
    s.z = fmaf(v[0].z, W2.x, s.z); s.z = fmaf(v[1].z, W2.y, s.z);
    s.z = fmaf(v[2].z, W2.z, s.z); s.z = fmaf(v[3].z, W2.w, s.z);
    s.w = fmaf(v[0].w, W3.x, s.w); s.w = fmaf(v[1].w, W3.y, s.w);
    s.w = fmaf(v[2].w, W3.z, s.w); s.w = fmaf(v[3].w, W3.w, s.w);

    float4 o;
    o.x = s.x / (1.f + __expf(-s.x));
    o.y = s.y / (1.f + __expf(-s.y));
    o.z = s.z / (1.f + __expf(-s.z));
    o.w = s.w / (1.f + __expf(-s.w));
    *(float4*)(g_xca + (size_t)bl * DI + d4) = o;
}

// ============== chunked scan: phase A ========================================
__global__ __launch_bounds__(64)
void scanA(const float* __restrict__ A_log)
{
    const int gwarp = blockIdx.x * 2 + (threadIdx.x >> 5);
    const int chunk = gwarp & (SC_NCH - 1);
    const int wpair = gwarp >> 4;
    const int lane  = threadIdx.x & 31;
    const int half  = lane >> 4;
    const int n     = lane & 15;
    const int c     = wpair * 2 + half;
    const int b     = c / DI;
    const int d     = c % DI;

    const float Aval = -__expf(A_log[d * DS + n]);

    const size_t rbase = (size_t)b * L_ * DI + d;
    const float* pD = g_del + rbase;
    const float* pX = g_xca + rbase;
    const float* pB = g_dBC + (size_t)b * L_ * 96 + DTR + n;

    float h = 0.f, P = 1.f;
    const int l0 = chunk * SC_CL;
    for (int q = 0; q < SC_CL; q++){
        const size_t l = (size_t)(l0 + q);
        float dlt = pD[l * DI];
        float xv  = pX[l * DI];
        float Bn  = pB[l * 96];
        float a = __expf(dlt * Aval);
        h = fmaf(a, h, dlt * Bn * xv);
        P *= a;
    }
    const size_t o = ((size_t)c * SC_NCH + chunk) * DS + n;
    g_hend [o] = h;
    g_aprod[o] = P;
}

// ============== chunked scan: phase B ========================================
__global__ __launch_bounds__(256)
void scanB(void)
{
    const int idx = blockIdx.x * 256 + threadIdx.x;
    if (idx >= B_ * DI * DS) return;
    const int c = idx >> 4;
    const int n = idx & 15;

    float h0 = 0.f;
#pragma unroll
    for (int j = 0; j < SC_NCH; j++){
        const size_t o = ((size_t)c * SC_NCH + j) * DS + n;
        g_h0[o] = h0;
        h0 = fmaf(g_aprod[o], h0, g_hend[o]);
    }
}

// ============== chunked scan: phase C ========================================
__global__ __launch_bounds__(64)
void scanC(const float* __restrict__ A_log, const float* __restrict__ Dp)
{
    const int gwarp = blockIdx.x * 2 + (threadIdx.x >> 5);
    const int chunk = gwarp & (SC_NCH - 1);
    const int wpair = gwarp >> 4;
    const int lane  = threadIdx.x & 31;
    const int half  = lane >> 4;
    const int n     = lane & 15;
    const int c     = wpair * 2 + half;
    const int b     = c / DI;
    const int d     = c % DI;

    const float Aval = -__expf(A_log[d * DS + n]);
    const float dp   = Dp[d];

    const size_t rbase = (size_t)b * L_ * DI + d;
    const float* pD = g_del + rbase;
    const float* pX = g_xca + rbase;
    const float* pZ = g_z   + rbase;
    const float* pB = g_dBC + (size_t)b * L_ * 96 + DTR + n;
    const float* pC = g_dBC + (size_t)b * L_ * 96 + DTR + DS + n;
    __half* pUh = g_uh + rbase;
    __half* pUl = g_ul + rbase;

    float h = g_h0[((size_t)c * SC_NCH + chunk) * DS + n];

    const int l0 = chunk * SC_CL;
    for (int q = 0; q < SC_CL; q++){
        const size_t l = (size_t)(l0 + q);
        float dlt = pD[l * DI];
        float xv  = pX[l * DI];
        float zv  = pZ[l * DI];
        float Bn  = pB[l * 96];
        float Cn  = pC[l * 96];

        float a = __expf(dlt * Aval);
        h = fmaf(a, h, dlt * Bn * xv);
        float p = h * Cn;
        p += __shfl_xor_sync(0xffffffffu, p, 8);
        p += __shfl_xor_sync(0xffffffffu, p, 4);
        p += __shfl_xor_sync(0xffffffffu, p, 2);
        p += __shfl_xor_sync(0xffffffffu, p, 1);
        if (n == 0){
            float y  = fmaf(dp, xv, p);
            float sz = zv / (1.f + __expf(-zv));
            float u  = y * sz;
            __half uh = __float2half_rn(u);
            __half ul = __float2half_rn(u - __half2float(uh));
            pUh[l * DI] = uh;
            pUl[l * DI] = ul;
        }
    }
}

// ---------------- launch ------------------------------------------------------
extern "C" void kernel_launch(void* const* d_in, const int* in_sizes, int n_in,
                              void* d_out, int out_size)
{
    const float* x      = (const float*)d_in[0];
    const float* W_in   = (const float*)d_in[1];
    const float* conv_w = (const float*)d_in[2];
    const float* conv_b = (const float*)d_in[3];
    const float* W_x    = (const float*)d_in[4];
    const float* W_dt   = (const float*)d_in[5];
    const float* b_dt   = (const float*)d_in[6];
    const float* A_log  = (const float*)d_in[7];
    const float* Dp     = (const float*)d_in[8];
    const float* W_out  = (const float*)d_in[9];
    float* out = (float*)d_out;

    float* p_xca; cudaGetSymbolAddress((void**)&p_xca, g_xca);
    float* p_dBC; cudaGetSymbolAddress((void**)&p_dBC, g_dBC);
    float* p_del; cudaGetSymbolAddress((void**)&p_del, g_del);

    __half *p_xh, *p_xl, *p_wih, *p_uh, *p_ul, *p_woh, *p_dch, *p_dcl, *p_wdh, *p_wdl;
    cudaGetSymbolAddress((void**)&p_xh,  g_xh);
    cudaGetSymbolAddress((void**)&p_xl,  g_xl);
    cudaGetSymbolAddress((void**)&p_wih, g_wih);
    cudaGetSymbolAddress((void**)&p_uh,  g_uh);
    cudaGetSymbolAddress((void**)&p_ul,  g_ul);
    cudaGetSymbolAddress((void**)&p_woh, g_woh);
    cudaGetSymbolAddress((void**)&p_dch, g_dch);
    cudaGetSymbolAddress((void**)&p_dcl, g_dcl);
    cudaGetSymbolAddress((void**)&p_wdh, g_wdh);
    cudaGetSymbolAddress((void**)&p_wdl, g_wdl);

    cudaFuncSetAttribute(mma_gemm<0>, cudaFuncAttributeMaxDynamicSharedMemorySize, MMA_SMEM_MAIN);
    cudaFuncSetAttribute(mma_gemm<1>, cudaFuncAttributeMaxDynamicSharedMemorySize, MMA_SMEM_MAIN);
    cudaFuncSetAttribute(mma_gemm<3>, cudaFuncAttributeMaxDynamicSharedMemorySize, MMA_SMEM_DELTA);

    // 1) prep: split x, cvt W_in, cvt W_out, split W_dt, zero dBC
    prep_kernel<<<PREP_BLOCKS, 256>>>(x, W_in, W_out, W_dt);

    // 2) xz = x @ W_in^T  (HMMA fp16x2) -> g_xc / g_z
    {
        dim3 grid(2 * DI / 128, BL / 128);
        mma_gemm<1><<<grid, 256, MMA_SMEM_MAIN>>>(p_xh, p_xl, p_wih, nullptr, nullptr,
                                                  DM, DM, nullptr, 0);
    }
    // 3) depthwise causal conv + bias + silu -> g_xca
    {
        int total = BL * DI / 4;
        conv_silu_kernel<<<(total + 255) / 256, 256>>>(conv_w, conv_b);
    }
    // 4) dBC = xca @ W_x^T  (64x96 tile, acc 4x6, split-K=8)   <- profiled slot
    {
        dim3 grid(SKS, BL / 64);
        gemm_small3<<<grid, 256>>>(p_xca, DI, W_x, DI, p_dBC, 96);
    }
    // 5) split dBC[:, :64] into fp16 hi/lo
    {
        split_dbc<<<(BL * 16 + 255) / 256, 256>>>();
    }
    // 6) delta = softplus(dBC[:, :64] @ W_dt^T + b_dt)  (HMMA fp16x3, K=64)
    {
        dim3 grid(DI / 128, BL / 128);
        mma_gemm<3><<<grid, 256, MMA_SMEM_DELTA>>>(p_dch, p_dcl, p_wdh, p_wdl, b_dt,
                                                   DTR, DTR, p_del, DI);
    }
    // 7) chunked selective scan
    {
        int nwarps = (B_ * DI / 2) * SC_NCH;
        scanA<<<nwarps / 2, 64>>>(A_log);
        scanB<<<(B_ * DI * DS + 255) / 256, 256>>>();
        scanC<<<nwarps / 2, 64>>>(A_log, Dp);
    }
    // 8) out = u @ W_out^T  (HMMA fp16x2)
    {
        dim3 grid(DM / 128, BL / 128);
        mma_gemm<0><<<grid, 256, MMA_SMEM_MAIN>>>(p_uh, p_ul, p_woh, nullptr, nullptr,
                                                  DI, DI, out, DM);
    }
}